// round 6
// baseline (speedup 1.0000x reference)
#include <cuda_runtime.h>

#define NB 16
#define SEQ 1024
#define DM 512
#define NH 8
#define HD 64
#define NROWS (NB*SEQ)          // 16384
#define OUT0 (NROWS*DM)         // 8388608 floats: out region, then weights

#define SQ_STR 68               // smem stride, [m][k]/[n][k] tiles, conflict-free frags
#define SV_STR 72               // smem stride for V [k][n] tiles (≡8 mod 32)
#define SS_STR 1028             // smem stride for 1024-wide score rows

__device__ float g_q[NROWS*DM];     // fp32 (relu'd) — residual + cvt at use
__device__ float g_k[NROWS*DM];     // tf32 bit patterns
__device__ float g_v[NROWS*DM];     // tf32 bit patterns
__device__ float g_att[NROWS*DM];
__device__ int   g_valid[NROWS];

#define NEGINF __int_as_float(0xff800000)

__device__ __forceinline__ unsigned f2tf(float x){
    unsigned r; asm("cvt.rna.tf32.f32 %0, %1;" : "=r"(r) : "f"(x)); return r;
}
__device__ __forceinline__ uint4 f2tf4(float4 v){
    return make_uint4(f2tf(v.x), f2tf(v.y), f2tf(v.z), f2tf(v.w));
}

// D += A(16x8 row) * B(8x8 col), tf32 in, fp32 accum
__device__ __forceinline__ void mma8(float c[4], const unsigned a[4], const unsigned b[2]){
    asm volatile("mma.sync.aligned.m16n8k8.row.col.f32.tf32.tf32.f32 "
        "{%0,%1,%2,%3}, {%4,%5,%6,%7}, {%8,%9}, {%0,%1,%2,%3};\n"
        : "+f"(c[0]), "+f"(c[1]), "+f"(c[2]), "+f"(c[3])
        : "r"(a[0]), "r"(a[1]), "r"(a[2]), "r"(a[3]), "r"(b[0]), "r"(b[1]));
}

// ---------------------------------------------------------------------------
// Kernel 1: per-row validity (row is padding iff all 512 features == 0)
// ---------------------------------------------------------------------------
__global__ void valid_kernel(const float* __restrict__ Q){
    int row  = blockIdx.x * 8 + (threadIdx.x >> 5);
    int lane = threadIdx.x & 31;
    const float4* p = (const float4*)(Q + (size_t)row * DM);
    bool nz = false;
    #pragma unroll
    for (int i = 0; i < 4; i++){
        float4 v = p[lane + i*32];
        nz |= (v.x != 0.f) || (v.y != 0.f) || (v.z != 0.f) || (v.w != 0.f);
    }
    unsigned m = __ballot_sync(0xffffffffu, nz);
    if (lane == 0) g_valid[row] = (m != 0u);
}

// ---------------------------------------------------------------------------
// Kernel 2: QKV projection  out = relu(Q @ W^T + b)
// Block tile 128x128, BK=32; 8 warps as 4x2, warp tile 32x64.
// q output fp32; k/v outputs pre-converted to tf32 bits.
// ---------------------------------------------------------------------------
__global__ __launch_bounds__(256, 2) void proj_kernel(
    const float* __restrict__ Q,
    const float* __restrict__ Wq, const float* __restrict__ bq,
    const float* __restrict__ Wk, const float* __restrict__ bk,
    const float* __restrict__ Wv, const float* __restrict__ bv)
{
    __shared__ unsigned As[128*36];
    __shared__ unsigned Bs[128*36];

    const int z = blockIdx.z;
    const float* W    = (z==0) ? Wq : (z==1) ? Wk : Wv;
    const float* bias = (z==0) ? bq : (z==1) ? bk : bv;
    float*       out  = (z==0) ? g_q : (z==1) ? g_k : g_v;

    const int m0 = blockIdx.y * 128, n0 = blockIdx.x * 128;
    const int tid = threadIdx.x, warp = tid >> 5, lane = tid & 31;
    const int wm = warp >> 1, wn = warp & 1;

    float acc[2][8][4];
    #pragma unroll
    for (int i=0;i<2;i++)
        #pragma unroll
        for (int j=0;j<8;j++)
            #pragma unroll
            for (int r=0;r<4;r++) acc[i][j][r] = 0.f;

    const int ar = tid >> 3, ac = (tid & 7) * 4;

    float4 pa[4], pb[4];
    #pragma unroll
    for (int i = 0; i < 4; i++){
        pa[i] = *(const float4*)(Q + (size_t)(m0 + ar + i*32)*DM + ac);
        pb[i] = *(const float4*)(W + (size_t)(n0 + ar + i*32)*DM + ac);
    }

    for (int kt = 0; kt < DM; kt += 32){
        __syncthreads();
        #pragma unroll
        for (int i = 0; i < 4; i++){
            *(uint4*)&As[(ar + i*32)*36 + ac] = f2tf4(pa[i]);
            *(uint4*)&Bs[(ar + i*32)*36 + ac] = f2tf4(pb[i]);
        }
        __syncthreads();
        if (kt + 32 < DM){
            #pragma unroll
            for (int i = 0; i < 4; i++){
                pa[i] = *(const float4*)(Q + (size_t)(m0 + ar + i*32)*DM + kt + 32 + ac);
                pb[i] = *(const float4*)(W + (size_t)(n0 + ar + i*32)*DM + kt + 32 + ac);
            }
        }
        #pragma unroll
        for (int ks = 0; ks < 32; ks += 8){
            const int cb = ks + (lane & 3);
            unsigned a[2][4];
            #pragma unroll
            for (int mi = 0; mi < 2; mi++){
                int r0 = wm*32 + mi*16 + (lane >> 2);
                a[mi][0] = As[ r0   *36 + cb];
                a[mi][1] = As[(r0+8)*36 + cb];
                a[mi][2] = As[ r0   *36 + cb + 4];
                a[mi][3] = As[(r0+8)*36 + cb + 4];
            }
            #pragma unroll
            for (int ni = 0; ni < 8; ni++){
                int c0 = wn*64 + ni*8 + (lane >> 2);
                unsigned bf[2] = { Bs[c0*36 + cb], Bs[c0*36 + cb + 4] };
                mma8(acc[0][ni], a[0], bf);
                mma8(acc[1][ni], a[1], bf);
            }
        }
    }

    #pragma unroll
    for (int mi = 0; mi < 2; mi++){
        #pragma unroll
        for (int ni = 0; ni < 8; ni++){
            int row = m0 + wm*32 + mi*16 + (lane >> 2);
            int col = n0 + wn*64 + ni*8 + (lane & 3)*2;
            float b0 = __ldg(bias + col), b1 = __ldg(bias + col + 1);
            float v00 = fmaxf(acc[mi][ni][0] + b0, 0.f), v01 = fmaxf(acc[mi][ni][1] + b1, 0.f);
            float v10 = fmaxf(acc[mi][ni][2] + b0, 0.f), v11 = fmaxf(acc[mi][ni][3] + b1, 0.f);
            if (z != 0){  // k/v: store tf32 bit patterns
                v00 = __uint_as_float(f2tf(v00)); v01 = __uint_as_float(f2tf(v01));
                v10 = __uint_as_float(f2tf(v10)); v11 = __uint_as_float(f2tf(v11));
            }
            *(float2*)(out + (size_t)row*DM + col)     = make_float2(v00, v01);
            *(float2*)(out + (size_t)(row+8)*DM + col) = make_float2(v10, v11);
        }
    }
}

// ---------------------------------------------------------------------------
// Kernel 3: fused scores + softmax + weights write + W@V + residual
// per (b, h, 32-row q-tile). 256 threads.
//   phase 1: scores (K tiles 256x64, reg double-buffered), warp tile 32x32 in n
//   phase 2: exact softmax, weights -> global, tf32 weights -> sS
//   phase 3: W@V k-split across 8 warps, V tiles 256x64 [k][n], smem reduction
// ---------------------------------------------------------------------------
__global__ __launch_bounds__(256) void score_kernel(float* __restrict__ wout){
    extern __shared__ unsigned smem[];
    unsigned* sQ  = smem;                        // 32 * 68
    unsigned* sKV = sQ + 32*SQ_STR;              // 256 * 72 (K: stride 68; V: stride 72; red)
    float*    sS  = (float*)(sKV + 256*SV_STR);  // 32 * 1028
    int*      sVK = (int*)(sS + 32*SS_STR);      // 1024
    int*      sVQ = sVK + SEQ;                   // 32

    const int b = blockIdx.z, h = blockIdx.y;
    const int q0 = blockIdx.x * 32;
    const int tid = threadIdx.x, warp = tid >> 5, lane = tid & 31;
    const int rowbase = b * SEQ;

    // load Q tile [32 x 64] (cvt to tf32)
    for (int i = tid; i < 512; i += 256){
        int r = i >> 4, c = (i & 15) * 4;
        float4 v = *(const float4*)(g_q + (size_t)(rowbase + q0 + r)*DM + h*HD + c);
        *(uint4*)&sQ[r*SQ_STR + c] = f2tf4(v);
    }
    for (int i = tid; i < SEQ; i += 256) sVK[i] = g_valid[rowbase + i];
    if (tid < 32) sVQ[tid] = g_valid[rowbase + q0 + tid];

    // ---- phase 1: scores ----
    uint4 pf[16];   // 256x64 tile prefetch (reused for V in phase 3)
    #pragma unroll
    for (int t = 0; t < 16; t++){
        int idx = tid + t*256, r = idx >> 4, c = (idx & 15) * 4;
        pf[t] = *(const uint4*)(g_k + (size_t)(rowbase + r)*DM + h*HD + c);
    }

    for (int kt = 0; kt < 4; kt++){
        const int k0 = kt * 256;
        __syncthreads();
        #pragma unroll
        for (int t = 0; t < 16; t++){
            int idx = tid + t*256, r = idx >> 4, c = (idx & 15) * 4;
            *(uint4*)&sKV[r*SQ_STR + c] = pf[t];
        }
        __syncthreads();
        if (kt < 3){
            #pragma unroll
            for (int t = 0; t < 16; t++){
                int idx = tid + t*256, r = idx >> 4, c = (idx & 15) * 4;
                pf[t] = *(const uint4*)(g_k + (size_t)(rowbase + k0 + 256 + r)*DM + h*HD + c);
            }
        }

        float acc[2][4][4];
        #pragma unroll
        for (int i=0;i<2;i++)
            #pragma unroll
            for (int j=0;j<4;j++)
                #pragma unroll
                for (int r=0;r<4;r++) acc[i][j][r] = 0.f;

        #pragma unroll
        for (int ks = 0; ks < 64; ks += 8){
            const int cb = ks + (lane & 3);
            unsigned a[2][4];
            #pragma unroll
            for (int mi = 0; mi < 2; mi++){
                int r0 = mi*16 + (lane >> 2);
                a[mi][0] = sQ[ r0   *SQ_STR + cb];
                a[mi][1] = sQ[(r0+8)*SQ_STR + cb];
                a[mi][2] = sQ[ r0   *SQ_STR + cb + 4];
                a[mi][3] = sQ[(r0+8)*SQ_STR + cb + 4];
            }
            #pragma unroll
            for (int ni = 0; ni < 4; ni++){
                int c0 = warp*32 + ni*8 + (lane >> 2);
                unsigned bf[2] = { sKV[c0*SQ_STR + cb], sKV[c0*SQ_STR + cb + 4] };
                mma8(acc[0][ni], a[0], bf);
                mma8(acc[1][ni], a[1], bf);
            }
        }
        #pragma unroll
        for (int mi = 0; mi < 2; mi++){
            #pragma unroll
            for (int ni = 0; ni < 4; ni++){
                int r  = mi*16 + (lane >> 2);
                int cl = warp*32 + ni*8 + (lane & 3)*2;
                bool v0 = sVK[k0 + cl] != 0, v1 = sVK[k0 + cl + 1] != 0;
                sS[ r   *SS_STR + k0 + cl    ] = v0 ? acc[mi][ni][0]*0.125f : NEGINF;
                sS[ r   *SS_STR + k0 + cl + 1] = v1 ? acc[mi][ni][1]*0.125f : NEGINF;
                sS[(r+8)*SS_STR + k0 + cl    ] = v0 ? acc[mi][ni][2]*0.125f : NEGINF;
                sS[(r+8)*SS_STR + k0 + cl + 1] = v1 ? acc[mi][ni][3]*0.125f : NEGINF;
            }
        }
    }
    __syncthreads();

    // ---- phase 2: softmax (one warp owns 4 rows) ----
    #pragma unroll 1
    for (int rr = 0; rr < 4; rr++){
        int r = warp*4 + rr;
        float* srow = sS + r*SS_STR;
        bool vq = sVQ[r] != 0;
        float vals[32];
        float m = NEGINF;
        #pragma unroll
        for (int j = 0; j < 32; j++){ vals[j] = srow[lane + j*32]; m = fmaxf(m, vals[j]); }
        #pragma unroll
        for (int o = 16; o > 0; o >>= 1) m = fmaxf(m, __shfl_xor_sync(0xffffffffu, m, o));
        float sum = 0.f;
        #pragma unroll
        for (int j = 0; j < 32; j++){ float p = __expf(vals[j] - m); vals[j] = p; sum += p; }
        #pragma unroll
        for (int o = 16; o > 0; o >>= 1) sum += __shfl_xor_sync(0xffffffffu, sum, o);
        float rs = vq ? (1.f / sum) : 0.f;    // invalid q-row: nan_to_num -> 0
        float* gw = wout + ((size_t)((b*NH + h)*SEQ + q0 + r)) * SEQ;
        unsigned* srowu = (unsigned*)srow;
        #pragma unroll
        for (int j = 0; j < 32; j++){
            float w = vals[j] * rs;
            gw[lane + j*32]    = w;
            srowu[lane + j*32] = f2tf(w);
        }
    }

    // ---- phase 3: attn = W @ V (k-split across 8 warps) ----
    #pragma unroll
    for (int t = 0; t < 16; t++){   // prefetch full 256x64 V tile 0
        int idx = tid + t*256, r = idx >> 4, c = (idx & 15) * 4;
        pf[t] = *(const uint4*)(g_v + (size_t)(rowbase + r)*DM + h*HD + c);
    }

    float acc[2][8][4];
    #pragma unroll
    for (int i=0;i<2;i++)
        #pragma unroll
        for (int j=0;j<8;j++)
            #pragma unroll
            for (int r=0;r<4;r++) acc[i][j][r] = 0.f;

    const unsigned* sSu = (const unsigned*)sS;
    for (int vt = 0; vt < 4; vt++){
        __syncthreads();
        #pragma unroll
        for (int t = 0; t < 16; t++){
            int idx = tid + t*256, r = idx >> 4, c = (idx & 15) * 4;
            *(uint4*)&sKV[r*SV_STR + c] = pf[t];
        }
        __syncthreads();
        if (vt < 3){
            #pragma unroll
            for (int t = 0; t < 16; t++){
                int idx = tid + t*256, r = idx >> 4, c = (idx & 15) * 4;
                pf[t] = *(const uint4*)(g_v + (size_t)(rowbase + (vt+1)*256 + r)*DM + h*HD + c);
            }
        }
        const int kbs = vt*256 + warp*32;   // this warp's k slice (cols in sS)
        const int kbv = warp*32;            // rows in sKV
        #pragma unroll
        for (int ks = 0; ks < 32; ks += 8){
            const int cbs = kbs + ks + (lane & 3);
            const int cbv = kbv + ks + (lane & 3);
            unsigned a[2][4];
            #pragma unroll
            for (int mi = 0; mi < 2; mi++){
                int r0 = mi*16 + (lane >> 2);
                a[mi][0] = sSu[ r0   *SS_STR + cbs];
                a[mi][1] = sSu[(r0+8)*SS_STR + cbs];
                a[mi][2] = sSu[ r0   *SS_STR + cbs + 4];
                a[mi][3] = sSu[(r0+8)*SS_STR + cbs + 4];
            }
            #pragma unroll
            for (int ni = 0; ni < 8; ni++){
                int c0 = ni*8 + (lane >> 2);
                unsigned bf[2] = { sKV[cbv*SV_STR + c0], sKV[(cbv+4)*SV_STR + c0] };
                mma8(acc[0][ni], a[0], bf);
                mma8(acc[1][ni], a[1], bf);
            }
        }
    }
    __syncthreads();

    // cross-warp reduction: warp w -> sKV rows [w*32, w*32+32), stride 72
    float* red = (float*)sKV;
    #pragma unroll
    for (int mi = 0; mi < 2; mi++){
        #pragma unroll
        for (int ni = 0; ni < 8; ni++){
            int r = mi*16 + (lane >> 2);
            int c = ni*8 + (lane & 3)*2;
            *(float2*)&red[(warp*32 + r    )*SV_STR + c] = make_float2(acc[mi][ni][0], acc[mi][ni][1]);
            *(float2*)&red[(warp*32 + r + 8)*SV_STR + c] = make_float2(acc[mi][ni][2], acc[mi][ni][3]);
        }
    }
    __syncthreads();

    #pragma unroll
    for (int o = 0; o < 2; o++){
        int idx = tid + o*256;
        int r = idx >> 4, c = (idx & 15) * 4;
        float4 s = make_float4(0.f, 0.f, 0.f, 0.f);
        #pragma unroll
        for (int w = 0; w < 8; w++){
            float4 v = *(const float4*)&red[(w*32 + r)*SV_STR + c];
            s.x += v.x; s.y += v.y; s.z += v.z; s.w += v.w;
        }
        size_t base = (size_t)(rowbase + q0 + r)*DM + h*HD + c;
        float4 q = *(const float4*)(g_q + base);
        *(float4*)(g_att + base) = make_float4(s.x + q.x, s.y + q.y, s.z + q.z, s.w + q.w);
    }
}

// ---------------------------------------------------------------------------
// Kernel 4: LayerNorm + relu, one block (128 thr) per row
// ---------------------------------------------------------------------------
__global__ __launch_bounds__(128) void ln_kernel(const float* __restrict__ lnw,
                                                 const float* __restrict__ lnb,
                                                 float* __restrict__ out){
    const int row = blockIdx.x, tid = threadIdx.x;
    const float4 x = *(const float4*)(g_att + (size_t)row*DM + tid*4);
    float s  = x.x + x.y + x.z + x.w;
    float ss = fmaf(x.x, x.x, fmaf(x.y, x.y, fmaf(x.z, x.z, x.w*x.w)));
    #pragma unroll
    for (int o = 16; o > 0; o >>= 1){
        s  += __shfl_xor_sync(0xffffffffu, s,  o);
        ss += __shfl_xor_sync(0xffffffffu, ss, o);
    }
    __shared__ float red[8];
    int warp = tid >> 5, lane = tid & 31;
    if (lane == 0){ red[warp] = s; red[warp+4] = ss; }
    __syncthreads();
    s  = red[0] + red[1] + red[2] + red[3];
    ss = red[4] + red[5] + red[6] + red[7];
    float mu  = s * (1.0f/DM);
    float inv = rsqrtf(ss * (1.0f/DM) - mu*mu + 1e-5f);
    const float4 w = *(const float4*)(lnw + tid*4);
    const float4 bb = *(const float4*)(lnb + tid*4);
    float4 y;
    y.x = fmaxf((x.x - mu)*inv*w.x + bb.x, 0.f);
    y.y = fmaxf((x.y - mu)*inv*w.y + bb.y, 0.f);
    y.z = fmaxf((x.z - mu)*inv*w.z + bb.z, 0.f);
    y.w = fmaxf((x.w - mu)*inv*w.w + bb.w, 0.f);
    *(float4*)(out + (size_t)row*DM + tid*4) = y;
}

// ---------------------------------------------------------------------------
extern "C" void kernel_launch(void* const* d_in, const int* in_sizes, int n_in,
                              void* d_out, int out_size){
    const float* Q   = (const float*)d_in[0];
    const float* Wq  = (const float*)d_in[1];
    const float* bq  = (const float*)d_in[2];
    const float* Wk  = (const float*)d_in[3];
    const float* bk  = (const float*)d_in[4];
    const float* Wv  = (const float*)d_in[5];
    const float* bv  = (const float*)d_in[6];
    const float* lnw = (const float*)d_in[7];
    const float* lnb = (const float*)d_in[8];
    float* out = (float*)d_out;

    valid_kernel<<<NROWS/8, 256>>>(Q);
    proj_kernel<<<dim3(DM/128, NROWS/128, 3), 256>>>(Q, Wq, bq, Wk, bk, Wv, bv);

    const int score_smem = (32*SQ_STR + 256*SV_STR + 32*SS_STR + SEQ + 32) * 4;  // 218240
    cudaFuncSetAttribute(score_kernel, cudaFuncAttributeMaxDynamicSharedMemorySize, score_smem);
    score_kernel<<<dim3(SEQ/32, NH, NB), 256, score_smem>>>(out + OUT0);

    ln_kernel<<<NROWS, 128>>>(lnw, lnb, out);
}

// round 8
// speedup vs baseline: 1.0525x; 1.0525x over previous
#include <cuda_runtime.h>

#define NB 16
#define SEQ 1024
#define DM 512
#define NH 8
#define HD 64
#define NROWS (NB*SEQ)          // 16384
#define OUT0 (NROWS*DM)         // 8388608 floats: out region, then weights

#define SQ_STR 68               // smem stride, [m][k]/[n][k] tiles, conflict-free frags
#define SV_STR 72               // smem stride for V [k][n] tiles (≡8 mod 32)
#define SS_STR 1028             // smem stride for 1024-wide score rows

__device__ float g_q[NROWS*DM];     // fp32 (relu'd) — residual + cvt at use
__device__ float g_k[NROWS*DM];     // tf32 bit patterns
__device__ float g_v[NROWS*DM];     // tf32 bit patterns
__device__ float g_att[NROWS*DM];
__device__ int   g_valid[NROWS];

#define NEGINF __int_as_float(0xff800000)

__device__ __forceinline__ unsigned f2tf(float x){
    unsigned r; asm("cvt.rna.tf32.f32 %0, %1;" : "=r"(r) : "f"(x)); return r;
}
__device__ __forceinline__ uint4 f2tf4(float4 v){
    return make_uint4(f2tf(v.x), f2tf(v.y), f2tf(v.z), f2tf(v.w));
}
__device__ __forceinline__ void cpasync16(unsigned s, const void* g){
    asm volatile("cp.async.cg.shared.global [%0], [%1], 16;" :: "r"(s), "l"(g));
}
#define CP_COMMIT() asm volatile("cp.async.commit_group;")
#define CP_WAIT(n)  asm volatile("cp.async.wait_group %0;" :: "n"(n))

// D += A(16x8 row) * B(8x8 col), tf32 in, fp32 accum
__device__ __forceinline__ void mma8(float c[4], const unsigned a[4], const unsigned b[2]){
    asm volatile("mma.sync.aligned.m16n8k8.row.col.f32.tf32.tf32.f32 "
        "{%0,%1,%2,%3}, {%4,%5,%6,%7}, {%8,%9}, {%0,%1,%2,%3};\n"
        : "+f"(c[0]), "+f"(c[1]), "+f"(c[2]), "+f"(c[3])
        : "r"(a[0]), "r"(a[1]), "r"(a[2]), "r"(a[3]), "r"(b[0]), "r"(b[1]));
}

// ---------------------------------------------------------------------------
// Kernel 1: per-row validity (row is padding iff all 512 features == 0)
// ---------------------------------------------------------------------------
__global__ void valid_kernel(const float* __restrict__ Q){
    int row  = blockIdx.x * 8 + (threadIdx.x >> 5);
    int lane = threadIdx.x & 31;
    const float4* p = (const float4*)(Q + (size_t)row * DM);
    bool nz = false;
    #pragma unroll
    for (int i = 0; i < 4; i++){
        float4 v = p[lane + i*32];
        nz |= (v.x != 0.f) || (v.y != 0.f) || (v.z != 0.f) || (v.w != 0.f);
    }
    unsigned m = __ballot_sync(0xffffffffu, nz);
    if (lane == 0) g_valid[row] = (m != 0u);
}

// ---------------------------------------------------------------------------
// Kernel 2: QKV projection  out = relu(Q @ W^T + b), tf32 mma
// Block tile 128x64, BK=32; 8 warps as 4x2, warp tile 32x32.
// Register double-buffered global loads. k/v outputs pre-converted to tf32.
// ---------------------------------------------------------------------------
__global__ __launch_bounds__(256) void proj_kernel(
    const float* __restrict__ Q,
    const float* __restrict__ Wq, const float* __restrict__ bq,
    const float* __restrict__ Wk, const float* __restrict__ bk,
    const float* __restrict__ Wv, const float* __restrict__ bv)
{
    __shared__ unsigned As[128*36];
    __shared__ unsigned Bs[64*36];

    const int z = blockIdx.z;
    const float* W    = (z==0) ? Wq : (z==1) ? Wk : Wv;
    const float* bias = (z==0) ? bq : (z==1) ? bk : bv;
    float*       out  = (z==0) ? g_q : (z==1) ? g_k : g_v;

    const int m0 = blockIdx.y * 128, n0 = blockIdx.x * 64;
    const int tid = threadIdx.x, warp = tid >> 5, lane = tid & 31;
    const int wm = warp >> 1, wn = warp & 1;

    float acc[2][4][4];
    #pragma unroll
    for (int i=0;i<2;i++)
        #pragma unroll
        for (int j=0;j<4;j++)
            #pragma unroll
            for (int r=0;r<4;r++) acc[i][j][r] = 0.f;

    const int ar = tid >> 3, ac = (tid & 7) * 4;

    float4 pa[4], pb[2];
    #pragma unroll
    for (int i = 0; i < 4; i++)
        pa[i] = *(const float4*)(Q + (size_t)(m0 + ar + i*32)*DM + ac);
    #pragma unroll
    for (int i = 0; i < 2; i++)
        pb[i] = *(const float4*)(W + (size_t)(n0 + ar + i*32)*DM + ac);

    for (int kt = 0; kt < DM; kt += 32){
        __syncthreads();
        #pragma unroll
        for (int i = 0; i < 4; i++)
            *(uint4*)&As[(ar + i*32)*36 + ac] = f2tf4(pa[i]);
        #pragma unroll
        for (int i = 0; i < 2; i++)
            *(uint4*)&Bs[(ar + i*32)*36 + ac] = f2tf4(pb[i]);
        __syncthreads();
        if (kt + 32 < DM){
            #pragma unroll
            for (int i = 0; i < 4; i++)
                pa[i] = *(const float4*)(Q + (size_t)(m0 + ar + i*32)*DM + kt + 32 + ac);
            #pragma unroll
            for (int i = 0; i < 2; i++)
                pb[i] = *(const float4*)(W + (size_t)(n0 + ar + i*32)*DM + kt + 32 + ac);
        }
        #pragma unroll
        for (int ks = 0; ks < 32; ks += 8){
            unsigned a[2][4];
            const int cb = ks + (lane & 3);
            #pragma unroll
            for (int mi = 0; mi < 2; mi++){
                int r0 = wm*32 + mi*16 + (lane >> 2);
                a[mi][0] = As[ r0   *36 + cb];
                a[mi][1] = As[(r0+8)*36 + cb];
                a[mi][2] = As[ r0   *36 + cb + 4];
                a[mi][3] = As[(r0+8)*36 + cb + 4];
            }
            #pragma unroll
            for (int ni = 0; ni < 4; ni++){
                int c0 = wn*32 + ni*8 + (lane >> 2);
                unsigned bf[2] = { Bs[c0*36 + cb], Bs[c0*36 + cb + 4] };
                mma8(acc[0][ni], a[0], bf);
                mma8(acc[1][ni], a[1], bf);
            }
        }
    }

    #pragma unroll
    for (int mi = 0; mi < 2; mi++){
        #pragma unroll
        for (int ni = 0; ni < 4; ni++){
            int row = m0 + wm*32 + mi*16 + (lane >> 2);
            int col = n0 + wn*32 + ni*8 + (lane & 3)*2;
            float b0 = __ldg(bias + col), b1 = __ldg(bias + col + 1);
            float v00 = fmaxf(acc[mi][ni][0] + b0, 0.f), v01 = fmaxf(acc[mi][ni][1] + b1, 0.f);
            float v10 = fmaxf(acc[mi][ni][2] + b0, 0.f), v11 = fmaxf(acc[mi][ni][3] + b1, 0.f);
            if (z != 0){  // k/v: store tf32 bit patterns
                v00 = __uint_as_float(f2tf(v00)); v01 = __uint_as_float(f2tf(v01));
                v10 = __uint_as_float(f2tf(v10)); v11 = __uint_as_float(f2tf(v11));
            }
            *(float2*)(out + (size_t)row*DM + col)     = make_float2(v00, v01);
            *(float2*)(out + (size_t)(row+8)*DM + col) = make_float2(v10, v11);
        }
    }
}

// ---------------------------------------------------------------------------
// Kernel 3: fused scores + softmax + weights write + W@V + residual
// per (b, h, 32-row q-tile). 256 threads.
//   phase 1: scores (K tiles 256x64, reg double-buffered; pf scoped)
//   phase 2: exact softmax, weights -> global, tf32 weights -> sS
//            (V tile 0 cp.async overlaps softmax)
//   phase 3: W@V, cp.async double-buffered 128-row V tiles, k-split 16/warp
// V tile copy audit: 128 rows x 64 cols = 2048 float4 = 8 iters x 256 thr. ✓
// ---------------------------------------------------------------------------
__global__ __launch_bounds__(256) void score_kernel(float* __restrict__ wout){
    extern __shared__ unsigned smem[];
    unsigned* sQ  = smem;                        // 32 * 68
    unsigned* sKV = sQ + 32*SQ_STR;              // 256 * 72 (K tiles / 2x128 V bufs / red)
    float*    sS  = (float*)(sKV + 256*SV_STR);  // 32 * 1028
    int*      sVK = (int*)(sS + 32*SS_STR);      // 1024
    int*      sVQ = sVK + SEQ;                   // 32

    const int b = blockIdx.z, h = blockIdx.y;
    const int q0 = blockIdx.x * 32;
    const int tid = threadIdx.x, warp = tid >> 5, lane = tid & 31;
    const int rowbase = b * SEQ;

    // load Q tile [32 x 64]: 512 elems = 2 iters x 256 thr x 1 float4? no:
    // 32x64 = 2048 floats = 512 float4 -> 2 iters x 256. ✓
    for (int i = tid; i < 512; i += 256){
        int r = i >> 4, c = (i & 15) * 4;
        float4 v = *(const float4*)(g_q + (size_t)(rowbase + q0 + r)*DM + h*HD + c);
        *(uint4*)&sQ[r*SQ_STR + c] = f2tf4(v);
    }
    for (int i = tid; i < SEQ; i += 256) sVK[i] = g_valid[rowbase + i];
    if (tid < 32) sVQ[tid] = g_valid[rowbase + q0 + tid];

    // ---- phase 1: scores ----
    {
        uint4 pf[16];   // 256x64 K tile = 4096 float4 = 16 x 256 thr. ✓
        #pragma unroll
        for (int t = 0; t < 16; t++){
            int idx = tid + t*256, r = idx >> 4, c = (idx & 15) * 4;
            pf[t] = *(const uint4*)(g_k + (size_t)(rowbase + r)*DM + h*HD + c);
        }

        for (int kt = 0; kt < 4; kt++){
            const int k0 = kt * 256;
            __syncthreads();
            #pragma unroll
            for (int t = 0; t < 16; t++){
                int idx = tid + t*256, r = idx >> 4, c = (idx & 15) * 4;
                *(uint4*)&sKV[r*SQ_STR + c] = pf[t];
            }
            __syncthreads();
            if (kt < 3){
                #pragma unroll
                for (int t = 0; t < 16; t++){
                    int idx = tid + t*256, r = idx >> 4, c = (idx & 15) * 4;
                    pf[t] = *(const uint4*)(g_k + (size_t)(rowbase + k0 + 256 + r)*DM + h*HD + c);
                }
            }

            float acc[2][4][4];
            #pragma unroll
            for (int i=0;i<2;i++)
                #pragma unroll
                for (int j=0;j<4;j++)
                    #pragma unroll
                    for (int r=0;r<4;r++) acc[i][j][r] = 0.f;

            #pragma unroll
            for (int ks = 0; ks < 64; ks += 8){
                const int cb = ks + (lane & 3);
                unsigned a[2][4];
                #pragma unroll
                for (int mi = 0; mi < 2; mi++){
                    int r0 = mi*16 + (lane >> 2);
                    a[mi][0] = sQ[ r0   *SQ_STR + cb];
                    a[mi][1] = sQ[(r0+8)*SQ_STR + cb];
                    a[mi][2] = sQ[ r0   *SQ_STR + cb + 4];
                    a[mi][3] = sQ[(r0+8)*SQ_STR + cb + 4];
                }
                #pragma unroll
                for (int ni = 0; ni < 4; ni++){
                    int c0 = warp*32 + ni*8 + (lane >> 2);
                    unsigned bf[2] = { sKV[c0*SQ_STR + cb], sKV[c0*SQ_STR + cb + 4] };
                    mma8(acc[0][ni], a[0], bf);
                    mma8(acc[1][ni], a[1], bf);
                }
            }
            #pragma unroll
            for (int mi = 0; mi < 2; mi++){
                #pragma unroll
                for (int ni = 0; ni < 4; ni++){
                    int r  = mi*16 + (lane >> 2);
                    int cl = warp*32 + ni*8 + (lane & 3)*2;
                    bool v0 = sVK[k0 + cl] != 0, v1 = sVK[k0 + cl + 1] != 0;
                    sS[ r   *SS_STR + k0 + cl    ] = v0 ? acc[mi][ni][0]*0.125f : NEGINF;
                    sS[ r   *SS_STR + k0 + cl + 1] = v1 ? acc[mi][ni][1]*0.125f : NEGINF;
                    sS[(r+8)*SS_STR + k0 + cl    ] = v0 ? acc[mi][ni][2]*0.125f : NEGINF;
                    sS[(r+8)*SS_STR + k0 + cl + 1] = v1 ? acc[mi][ni][3]*0.125f : NEGINF;
                }
            }
        }
    }
    __syncthreads();

    // issue V tile 0 -> buf0 (overlaps with softmax below)
    // 128x64 tile = 2048 float4 = 8 iters x 256 thr. ✓
    const unsigned svb = (unsigned)__cvta_generic_to_shared(sKV);
    const float* gV = g_v + (size_t)rowbase*DM + h*HD;
    #pragma unroll
    for (int t2 = 0; t2 < 8; t2++){
        int idx = tid + t2*256, r = idx >> 4, c = (idx & 15) * 4;
        cpasync16(svb + ((unsigned)(r*SV_STR + c))*4u, gV + (size_t)r*DM + c);
    }
    CP_COMMIT();

    // ---- phase 2: softmax (one warp owns 4 rows) ----
    #pragma unroll 1
    for (int rr = 0; rr < 4; rr++){
        int r = warp*4 + rr;
        float* srow = sS + r*SS_STR;
        bool vq = sVQ[r] != 0;
        float vals[32];
        float m = NEGINF;
        #pragma unroll
        for (int j = 0; j < 32; j++){ vals[j] = srow[lane + j*32]; m = fmaxf(m, vals[j]); }
        #pragma unroll
        for (int o = 16; o > 0; o >>= 1) m = fmaxf(m, __shfl_xor_sync(0xffffffffu, m, o));
        float sum = 0.f;
        #pragma unroll
        for (int j = 0; j < 32; j++){ float p = __expf(vals[j] - m); vals[j] = p; sum += p; }
        #pragma unroll
        for (int o = 16; o > 0; o >>= 1) sum += __shfl_xor_sync(0xffffffffu, sum, o);
        float rs = vq ? (1.f / sum) : 0.f;    // invalid q-row: nan_to_num -> 0
        float* gw = wout + ((size_t)((b*NH + h)*SEQ + q0 + r)) * SEQ;
        unsigned* srowu = (unsigned*)srow;
        #pragma unroll
        for (int j = 0; j < 32; j++){
            float w = vals[j] * rs;
            gw[lane + j*32]    = w;
            srowu[lane + j*32] = f2tf(w);
        }
    }

    // ---- phase 3: attn = W @ V, 8 tiles of 128 rows, cp.async dbl-buffer ----
    float acc[2][8][4];
    #pragma unroll
    for (int i=0;i<2;i++)
        #pragma unroll
        for (int j=0;j<8;j++)
            #pragma unroll
            for (int r=0;r<4;r++) acc[i][j][r] = 0.f;

    const unsigned* sSu = (const unsigned*)sS;
    #pragma unroll 1
    for (int vt = 0; vt < 8; vt++){
        const int cur = (vt & 1) * 128;
        if (vt < 7){
            const int nxt = ((vt+1) & 1) * 128;
            #pragma unroll
            for (int t2 = 0; t2 < 8; t2++){
                int idx = tid + t2*256, r = idx >> 4, c = (idx & 15) * 4;
                cpasync16(svb + ((unsigned)((nxt + r)*SV_STR + c))*4u,
                          gV + (size_t)((vt+1)*128 + r)*DM + c);
            }
            CP_COMMIT();
            CP_WAIT(1);
        } else {
            CP_WAIT(0);
        }
        __syncthreads();

        #pragma unroll
        for (int ks = 0; ks < 16; ks += 8){
            const int cbs = vt*128 + warp*16 + ks + (lane & 3);   // sS col
            const int cbv = cur + warp*16 + ks + (lane & 3);      // sKV row
            unsigned a[2][4];
            #pragma unroll
            for (int mi = 0; mi < 2; mi++){
                int r0 = mi*16 + (lane >> 2);
                a[mi][0] = sSu[ r0   *SS_STR + cbs];
                a[mi][1] = sSu[(r0+8)*SS_STR + cbs];
                a[mi][2] = sSu[ r0   *SS_STR + cbs + 4];
                a[mi][3] = sSu[(r0+8)*SS_STR + cbs + 4];
            }
            #pragma unroll
            for (int ni = 0; ni < 8; ni++){
                int c0 = ni*8 + (lane >> 2);
                unsigned bf[2] = { sKV[cbv*SV_STR + c0], sKV[(cbv+4)*SV_STR + c0] };
                mma8(acc[0][ni], a[0], bf);
                mma8(acc[1][ni], a[1], bf);
            }
        }
        __syncthreads();   // buffer 'cur' free for vt+2's cp.async
    }

    // cross-warp reduction: warp w -> sKV rows [w*32, w*32+32), stride 72
    float* red = (float*)sKV;
    #pragma unroll
    for (int mi = 0; mi < 2; mi++){
        #pragma unroll
        for (int ni = 0; ni < 8; ni++){
            int r = mi*16 + (lane >> 2);
            int c = ni*8 + (lane & 3)*2;
            *(float2*)&red[(warp*32 + r    )*SV_STR + c] = make_float2(acc[mi][ni][0], acc[mi][ni][1]);
            *(float2*)&red[(warp*32 + r + 8)*SV_STR + c] = make_float2(acc[mi][ni][2], acc[mi][ni][3]);
        }
    }
    __syncthreads();

    // 32x64 output = 512 float4 = 2 iters x 256 thr. ✓
    #pragma unroll
    for (int o = 0; o < 2; o++){
        int idx = tid + o*256;
        int r = idx >> 4, c = (idx & 15) * 4;
        float4 s = make_float4(0.f, 0.f, 0.f, 0.f);
        #pragma unroll
        for (int w = 0; w < 8; w++){
            float4 v = *(const float4*)&red[(w*32 + r)*SV_STR + c];
            s.x += v.x; s.y += v.y; s.z += v.z; s.w += v.w;
        }
        size_t base = (size_t)(rowbase + q0 + r)*DM + h*HD + c;
        float4 q = *(const float4*)(g_q + base);
        *(float4*)(g_att + base) = make_float4(s.x + q.x, s.y + q.y, s.z + q.z, s.w + q.w);
    }
}

// ---------------------------------------------------------------------------
// Kernel 4: LayerNorm + relu, one block (128 thr) per row
// ---------------------------------------------------------------------------
__global__ __launch_bounds__(128) void ln_kernel(const float* __restrict__ lnw,
                                                 const float* __restrict__ lnb,
                                                 float* __restrict__ out){
    const int row = blockIdx.x, tid = threadIdx.x;
    const float4 x = *(const float4*)(g_att + (size_t)row*DM + tid*4);
    float s  = x.x + x.y + x.z + x.w;
    float ss = fmaf(x.x, x.x, fmaf(x.y, x.y, fmaf(x.z, x.z, x.w*x.w)));
    #pragma unroll
    for (int o = 16; o > 0; o >>= 1){
        s  += __shfl_xor_sync(0xffffffffu, s,  o);
        ss += __shfl_xor_sync(0xffffffffu, ss, o);
    }
    __shared__ float red[8];
    int warp = tid >> 5, lane = tid & 31;
    if (lane == 0){ red[warp] = s; red[warp+4] = ss; }
    __syncthreads();
    s  = red[0] + red[1] + red[2] + red[3];
    ss = red[4] + red[5] + red[6] + red[7];
    float mu  = s * (1.0f/DM);
    float inv = rsqrtf(ss * (1.0f/DM) - mu*mu + 1e-5f);
    const float4 w = *(const float4*)(lnw + tid*4);
    const float4 bb = *(const float4*)(lnb + tid*4);
    float4 y;
    y.x = fmaxf((x.x - mu)*inv*w.x + bb.x, 0.f);
    y.y = fmaxf((x.y - mu)*inv*w.y + bb.y, 0.f);
    y.z = fmaxf((x.z - mu)*inv*w.z + bb.z, 0.f);
    y.w = fmaxf((x.w - mu)*inv*w.w + bb.w, 0.f);
    *(float4*)(out + (size_t)row*DM + tid*4) = y;
}

// ---------------------------------------------------------------------------
extern "C" void kernel_launch(void* const* d_in, const int* in_sizes, int n_in,
                              void* d_out, int out_size){
    const float* Q   = (const float*)d_in[0];
    const float* Wq  = (const float*)d_in[1];
    const float* bq  = (const float*)d_in[2];
    const float* Wk  = (const float*)d_in[3];
    const float* bk  = (const float*)d_in[4];
    const float* Wv  = (const float*)d_in[5];
    const float* bv  = (const float*)d_in[6];
    const float* lnw = (const float*)d_in[7];
    const float* lnb = (const float*)d_in[8];
    float* out = (float*)d_out;

    valid_kernel<<<NROWS/8, 256>>>(Q);
    proj_kernel<<<dim3(DM/64, NROWS/128, 3), 256>>>(Q, Wq, bq, Wk, bk, Wv, bv);

    const int score_smem = (32*SQ_STR + 256*SV_STR + 32*SS_STR + SEQ + 32) * 4;  // 218240
    cudaFuncSetAttribute(score_kernel, cudaFuncAttributeMaxDynamicSharedMemorySize, score_smem);
    score_kernel<<<dim3(SEQ/32, NH, NB), 256, score_smem>>>(out + OUT0);

    ln_kernel<<<NROWS, 128>>>(lnw, lnb, out);
}

// round 9
// speedup vs baseline: 1.3037x; 1.2387x over previous
#include <cuda_runtime.h>

#define NB 16
#define SEQ 1024
#define DM 512
#define NH 8
#define HD 64
#define NROWS (NB*SEQ)          // 16384
#define OUT0 (NROWS*DM)         // 8388608 floats: out region, then weights

#define SQ_STR 68               // smem stride for [rows][64] tf32 tiles (conflict-free frags)
#define SV_STR 72               // smem stride for V [k][n] tiles (≡8 mod 32)
#define KT_U   (128*SQ_STR)     // one 128x64 K-tile in uint units

__device__ float g_q[NROWS*DM];     // fp32 (relu'd)
__device__ float g_k[NROWS*DM];     // tf32 bit patterns
__device__ float g_v[NROWS*DM];     // tf32 bit patterns
__device__ float g_att[NROWS*DM];
__device__ int   g_valid[NROWS];

__device__ __forceinline__ unsigned f2tf(float x){
    unsigned r; asm("cvt.rna.tf32.f32 %0, %1;" : "=r"(r) : "f"(x)); return r;
}
__device__ __forceinline__ uint4 f2tf4(float4 v){
    return make_uint4(f2tf(v.x), f2tf(v.y), f2tf(v.z), f2tf(v.w));
}
__device__ __forceinline__ void cpasync16(unsigned s, const void* g){
    asm volatile("cp.async.cg.shared.global [%0], [%1], 16;" :: "r"(s), "l"(g));
}
#define CP_COMMIT() asm volatile("cp.async.commit_group;")
#define CP_WAIT(n)  asm volatile("cp.async.wait_group %0;" :: "n"(n))

// D += A(16x8 row) * B(8x8 col), tf32 in, fp32 accum
__device__ __forceinline__ void mma8(float c[4], const unsigned a[4], const unsigned b[2]){
    asm volatile("mma.sync.aligned.m16n8k8.row.col.f32.tf32.tf32.f32 "
        "{%0,%1,%2,%3}, {%4,%5,%6,%7}, {%8,%9}, {%0,%1,%2,%3};\n"
        : "+f"(c[0]), "+f"(c[1]), "+f"(c[2]), "+f"(c[3])
        : "r"(a[0]), "r"(a[1]), "r"(a[2]), "r"(a[3]), "r"(b[0]), "r"(b[1]));
}

// ---------------------------------------------------------------------------
// Kernel 1: per-row validity (row is padding iff all 512 features == 0)
// ---------------------------------------------------------------------------
__global__ void valid_kernel(const float* __restrict__ Q){
    int row  = blockIdx.x * 8 + (threadIdx.x >> 5);
    int lane = threadIdx.x & 31;
    const float4* p = (const float4*)(Q + (size_t)row * DM);
    bool nz = false;
    #pragma unroll
    for (int i = 0; i < 4; i++){
        float4 v = p[lane + i*32];
        nz |= (v.x != 0.f) || (v.y != 0.f) || (v.z != 0.f) || (v.w != 0.f);
    }
    unsigned m = __ballot_sync(0xffffffffu, nz);
    if (lane == 0) g_valid[row] = (m != 0u);
}

// ---------------------------------------------------------------------------
// Kernel 2: QKV projection  out = relu(Q @ W^T + b), tf32 mma
// Block tile 128x64, BK=32; 8 warps as 4x2, warp tile 32x32.
// Register double-buffered loads. k/v outputs pre-converted to tf32.
// ---------------------------------------------------------------------------
__global__ __launch_bounds__(256) void proj_kernel(
    const float* __restrict__ Q,
    const float* __restrict__ Wq, const float* __restrict__ bq,
    const float* __restrict__ Wk, const float* __restrict__ bk,
    const float* __restrict__ Wv, const float* __restrict__ bv)
{
    __shared__ unsigned As[128*36];
    __shared__ unsigned Bs[64*36];

    const int z = blockIdx.z;
    const float* W    = (z==0) ? Wq : (z==1) ? Wk : Wv;
    const float* bias = (z==0) ? bq : (z==1) ? bk : bv;
    float*       out  = (z==0) ? g_q : (z==1) ? g_k : g_v;

    const int m0 = blockIdx.y * 128, n0 = blockIdx.x * 64;
    const int tid = threadIdx.x, warp = tid >> 5, lane = tid & 31;
    const int wm = warp >> 1, wn = warp & 1;

    float acc[2][4][4];
    #pragma unroll
    for (int i=0;i<2;i++)
        #pragma unroll
        for (int j=0;j<4;j++)
            #pragma unroll
            for (int r=0;r<4;r++) acc[i][j][r] = 0.f;

    const int ar = tid >> 3, ac = (tid & 7) * 4;

    float4 pa[4], pb[2];
    #pragma unroll
    for (int i = 0; i < 4; i++)
        pa[i] = *(const float4*)(Q + (size_t)(m0 + ar + i*32)*DM + ac);
    #pragma unroll
    for (int i = 0; i < 2; i++)
        pb[i] = *(const float4*)(W + (size_t)(n0 + ar + i*32)*DM + ac);

    for (int kt = 0; kt < DM; kt += 32){
        __syncthreads();
        #pragma unroll
        for (int i = 0; i < 4; i++)
            *(uint4*)&As[(ar + i*32)*36 + ac] = f2tf4(pa[i]);
        #pragma unroll
        for (int i = 0; i < 2; i++)
            *(uint4*)&Bs[(ar + i*32)*36 + ac] = f2tf4(pb[i]);
        __syncthreads();
        if (kt + 32 < DM){
            #pragma unroll
            for (int i = 0; i < 4; i++)
                pa[i] = *(const float4*)(Q + (size_t)(m0 + ar + i*32)*DM + kt + 32 + ac);
            #pragma unroll
            for (int i = 0; i < 2; i++)
                pb[i] = *(const float4*)(W + (size_t)(n0 + ar + i*32)*DM + kt + 32 + ac);
        }
        #pragma unroll
        for (int ks = 0; ks < 32; ks += 8){
            unsigned a[2][4];
            const int cb = ks + (lane & 3);
            #pragma unroll
            for (int mi = 0; mi < 2; mi++){
                int r0 = wm*32 + mi*16 + (lane >> 2);
                a[mi][0] = As[ r0   *36 + cb];
                a[mi][1] = As[(r0+8)*36 + cb];
                a[mi][2] = As[ r0   *36 + cb + 4];
                a[mi][3] = As[(r0+8)*36 + cb + 4];
            }
            #pragma unroll
            for (int ni = 0; ni < 4; ni++){
                int c0 = wn*32 + ni*8 + (lane >> 2);
                unsigned bf[2] = { Bs[c0*36 + cb], Bs[c0*36 + cb + 4] };
                mma8(acc[0][ni], a[0], bf);
                mma8(acc[1][ni], a[1], bf);
            }
        }
    }

    #pragma unroll
    for (int mi = 0; mi < 2; mi++){
        #pragma unroll
        for (int ni = 0; ni < 4; ni++){
            int row = m0 + wm*32 + mi*16 + (lane >> 2);
            int col = n0 + wn*32 + ni*8 + (lane & 3)*2;
            float b0 = __ldg(bias + col), b1 = __ldg(bias + col + 1);
            float v00 = fmaxf(acc[mi][ni][0] + b0, 0.f), v01 = fmaxf(acc[mi][ni][1] + b1, 0.f);
            float v10 = fmaxf(acc[mi][ni][2] + b0, 0.f), v11 = fmaxf(acc[mi][ni][3] + b1, 0.f);
            if (z != 0){  // k/v: store tf32 bit patterns
                v00 = __uint_as_float(f2tf(v00)); v01 = __uint_as_float(f2tf(v01));
                v10 = __uint_as_float(f2tf(v10)); v11 = __uint_as_float(f2tf(v11));
            }
            *(float2*)(out + (size_t)row*DM + col)     = make_float2(v00, v01);
            *(float2*)(out + (size_t)(row+8)*DM + col) = make_float2(v10, v11);
        }
    }
}

// ---------------------------------------------------------------------------
// Kernel 3: escore — no-max softmax, two streaming passes over K.
// Per (b, h, 128-row q-tile), 256 thr, 8 warps as 4(m) x 2(n), warp tile 32x64.
// pass 0: acc -> exp (masked->0) -> row sums (regs only)
// pass 1: recompute, write FINAL normalized weights = e * rs to d_out.
// K tiles 128x64, cp.async double-buffered (tc = pass*8+kt, buffer = tc&1).
// smem ~110 KB -> 2 CTAs/SM.
// ---------------------------------------------------------------------------
__global__ __launch_bounds__(256, 2) void escore_kernel(float* __restrict__ wout){
    extern __shared__ unsigned smem[];
    unsigned* sQ   = smem;                   // 128*68
    unsigned* sK   = sQ + 128*SQ_STR;        // 2 * 128*68
    int*      sVK  = (int*)(sK + 2*KT_U);    // 1024
    float*    sRS2 = (float*)(sVK + SEQ);    // 256
    float*    sRS  = sRS2 + 256;             // 128

    const int b = blockIdx.z, h = blockIdx.y;
    const int q0 = blockIdx.x * 128;
    const int tid = threadIdx.x, warp = tid >> 5, lane = tid & 31;
    const int wm = warp >> 1, wn = warp & 1;
    const int rowbase = b * SEQ;

    // Q tile [128 x 64] -> tf32 smem: 2048 float4 = 8 x 256 thr. ✓
    #pragma unroll
    for (int t = 0; t < 8; t++){
        int idx = tid + t*256, r = idx >> 4, c = (idx & 15) * 4;
        float4 v = *(const float4*)(g_q + (size_t)(rowbase + q0 + r)*DM + h*HD + c);
        *(uint4*)&sQ[r*SQ_STR + c] = f2tf4(v);
    }
    for (int i = tid; i < SEQ; i += 256) sVK[i] = g_valid[rowbase + i];
    __syncthreads();

    // q-valid for this thread's 4 rows (j = mi*2+hh)
    bool vqa[4];
    #pragma unroll
    for (int j = 0; j < 4; j++)
        vqa[j] = sVK[q0 + wm*32 + (j>>1)*16 + (j&1)*8 + (lane>>2)] != 0;

    const unsigned skb = (unsigned)__cvta_generic_to_shared(sK);
    const float* gK = g_k + (size_t)rowbase*DM + h*HD;

    // prefetch K tile 0 -> buf0 (128x64 = 2048 float4 = 8 x 256 thr ✓)
    #pragma unroll
    for (int t2 = 0; t2 < 8; t2++){
        int idx = tid + t2*256, r = idx >> 4, c = (idx & 15) * 4;
        cpasync16(skb + ((unsigned)(r*SQ_STR + c))*4u, gK + (size_t)r*DM + c);
    }
    CP_COMMIT();

    float rsum[4] = {0.f, 0.f, 0.f, 0.f};
    float rs[4]   = {0.f, 0.f, 0.f, 0.f};

    #pragma unroll 1
    for (int pass = 0; pass < 2; pass++){
        #pragma unroll 1
        for (int kt = 0; kt < 8; kt++){
            const int tc = pass*8 + kt;
            const unsigned* sKc = sK + (tc & 1)*KT_U;
            if (tc < 15){
                const int nk = (tc + 1) & 7;
                const unsigned nb = skb + (unsigned)(((tc+1) & 1)*KT_U)*4u;
                #pragma unroll
                for (int t2 = 0; t2 < 8; t2++){
                    int idx = tid + t2*256, r = idx >> 4, c = (idx & 15) * 4;
                    cpasync16(nb + ((unsigned)(r*SQ_STR + c))*4u,
                              gK + (size_t)(nk*128 + r)*DM + c);
                }
                CP_COMMIT();
                CP_WAIT(1);
            } else {
                CP_WAIT(0);
            }
            __syncthreads();

            float acc[2][8][4];
            #pragma unroll
            for (int i=0;i<2;i++)
                #pragma unroll
                for (int j=0;j<8;j++)
                    #pragma unroll
                    for (int r=0;r<4;r++) acc[i][j][r] = 0.f;

            #pragma unroll
            for (int ks = 0; ks < 64; ks += 8){
                const int cb = ks + (lane & 3);
                unsigned a[2][4];
                #pragma unroll
                for (int mi = 0; mi < 2; mi++){
                    int r0 = wm*32 + mi*16 + (lane >> 2);
                    a[mi][0] = sQ[ r0   *SQ_STR + cb];
                    a[mi][1] = sQ[(r0+8)*SQ_STR + cb];
                    a[mi][2] = sQ[ r0   *SQ_STR + cb + 4];
                    a[mi][3] = sQ[(r0+8)*SQ_STR + cb + 4];
                }
                #pragma unroll
                for (int ni = 0; ni < 8; ni++){
                    int c0 = wn*64 + ni*8 + (lane >> 2);
                    unsigned bf[2] = { sKc[c0*SQ_STR + cb], sKc[c0*SQ_STR + cb + 4] };
                    mma8(acc[0][ni], a[0], bf);
                    mma8(acc[1][ni], a[1], bf);
                }
            }

            // epilogue: exp(masked) -> rowsum (pass0) or normalized store (pass1)
            #pragma unroll
            for (int mi = 0; mi < 2; mi++){
                #pragma unroll
                for (int ni = 0; ni < 8; ni++){
                    const int cl = kt*128 + wn*64 + ni*8 + (lane & 3)*2;
                    const bool v0 = sVK[cl] != 0, v1 = sVK[cl+1] != 0;
                    float e0 = (vqa[mi*2  ] && v0) ? __expf(acc[mi][ni][0]*0.125f) : 0.f;
                    float e1 = (vqa[mi*2  ] && v1) ? __expf(acc[mi][ni][1]*0.125f) : 0.f;
                    float e2 = (vqa[mi*2+1] && v0) ? __expf(acc[mi][ni][2]*0.125f) : 0.f;
                    float e3 = (vqa[mi*2+1] && v1) ? __expf(acc[mi][ni][3]*0.125f) : 0.f;
                    if (pass == 0){
                        rsum[mi*2  ] += e0 + e1;
                        rsum[mi*2+1] += e2 + e3;
                    } else {
                        size_t rg = (size_t)((b*NH + h)*SEQ + q0 + wm*32 + mi*16 + (lane>>2));
                        *(float2*)(wout + rg*SEQ + cl) =
                            make_float2(e0*rs[mi*2], e1*rs[mi*2]);
                        *(float2*)(wout + (rg+8)*SEQ + cl) =
                            make_float2(e2*rs[mi*2+1], e3*rs[mi*2+1]);
                    }
                }
            }
            __syncthreads();   // all warps done with this buffer before reuse
        }

        if (pass == 0){
            // reduce rowsums: quad shfl, then combine the two n-warps via smem
            #pragma unroll
            for (int j = 0; j < 4; j++){
                rsum[j] += __shfl_xor_sync(0xffffffffu, rsum[j], 1);
                rsum[j] += __shfl_xor_sync(0xffffffffu, rsum[j], 2);
            }
            if ((lane & 3) == 0){
                #pragma unroll
                for (int j = 0; j < 4; j++){
                    int row = wm*32 + (j>>1)*16 + (j&1)*8 + (lane>>2);
                    sRS2[wn*128 + row] = rsum[j];
                }
            }
            __syncthreads();
            if (tid < 128){
                float s = sRS2[tid] + sRS2[128 + tid];
                sRS[tid] = (s > 0.f) ? (1.f / s) : 0.f;   // invalid q-row -> 0
            }
            __syncthreads();
            #pragma unroll
            for (int j = 0; j < 4; j++)
                rs[j] = sRS[wm*32 + (j>>1)*16 + (j&1)*8 + (lane>>2)];
        }
    }
}

// ---------------------------------------------------------------------------
// Kernel 4: attn = W @ V + residual (reads normalized weights from d_out)
// Per (b,h): [1024x1024]@[1024x64]. Block 128x64, k-tile 64, 8 warps 4x2.
// V in [k][n] smem, stride 72, raw tf32 (pre-converted). (R4-proven)
// ---------------------------------------------------------------------------
__global__ __launch_bounds__(256) void wv_kernel(const float* __restrict__ wout){
    extern __shared__ unsigned smem[];
    unsigned* sW = smem;              // 128 * 68  ([m][k], tf32)
    unsigned* sV = sW + 128*SQ_STR;   // 64 * 72   ([k][n], tf32)

    const int b = blockIdx.z, h = blockIdx.y;
    const int m0 = blockIdx.x * 128;
    const int tid = threadIdx.x, warp = tid >> 5, lane = tid & 31;
    const int rowbase = b * SEQ;
    const int wm = warp >> 1, wn = warp & 1;
    const float* Wg = wout + (size_t)((b*NH + h)*SEQ + m0) * SEQ;

    float acc[2][4][4];
    #pragma unroll
    for (int i=0;i<2;i++)
        #pragma unroll
        for (int j=0;j<4;j++)
            #pragma unroll
            for (int r=0;r<4;r++) acc[i][j][r] = 0.f;

    float4 pw[8]; uint4 pv[4];
    #pragma unroll
    for (int t = 0; t < 8; t++){
        int idx = tid + t*256, r = idx >> 4, c = (idx & 15) * 4;
        pw[t] = *(const float4*)(Wg + (size_t)r*SEQ + c);
    }
    #pragma unroll
    for (int t = 0; t < 4; t++){
        int idx = tid + t*256, r = idx >> 4, c = (idx & 15) * 4;
        pv[t] = *(const uint4*)(g_v + (size_t)(rowbase + r)*DM + h*HD + c);
    }

    for (int kt = 0; kt < 16; kt++){
        const int k0 = kt * 64;
        __syncthreads();
        #pragma unroll
        for (int t = 0; t < 8; t++){
            int idx = tid + t*256, r = idx >> 4, c = (idx & 15) * 4;
            *(uint4*)&sW[r*SQ_STR + c] = f2tf4(pw[t]);
        }
        #pragma unroll
        for (int t = 0; t < 4; t++){
            int idx = tid + t*256, r = idx >> 4, c = (idx & 15) * 4;
            *(uint4*)&sV[r*SV_STR + c] = pv[t];
        }
        __syncthreads();
        if (kt < 15){
            #pragma unroll
            for (int t = 0; t < 8; t++){
                int idx = tid + t*256, r = idx >> 4, c = (idx & 15) * 4;
                pw[t] = *(const float4*)(Wg + (size_t)r*SEQ + k0 + 64 + c);
            }
            #pragma unroll
            for (int t = 0; t < 4; t++){
                int idx = tid + t*256, r = idx >> 4, c = (idx & 15) * 4;
                pv[t] = *(const uint4*)(g_v + (size_t)(rowbase + k0 + 64 + r)*DM + h*HD + c);
            }
        }
        #pragma unroll
        for (int ks = 0; ks < 64; ks += 8){
            const int cb = ks + (lane & 3);
            unsigned a[2][4];
            #pragma unroll
            for (int mi = 0; mi < 2; mi++){
                int r0 = wm*32 + mi*16 + (lane >> 2);
                a[mi][0] = sW[ r0   *SQ_STR + cb];
                a[mi][1] = sW[(r0+8)*SQ_STR + cb];
                a[mi][2] = sW[ r0   *SQ_STR + cb + 4];
                a[mi][3] = sW[(r0+8)*SQ_STR + cb + 4];
            }
            #pragma unroll
            for (int ni = 0; ni < 4; ni++){
                int c0 = wn*32 + ni*8 + (lane >> 2);
                unsigned bf[2] = { sV[cb*SV_STR + c0], sV[(cb+4)*SV_STR + c0] };
                mma8(acc[0][ni], a[0], bf);
                mma8(acc[1][ni], a[1], bf);
            }
        }
    }

    #pragma unroll
    for (int mi = 0; mi < 2; mi++){
        #pragma unroll
        for (int ni = 0; ni < 4; ni++){
            int r  = m0 + wm*32 + mi*16 + (lane >> 2);
            int cl = h*HD + wn*32 + ni*8 + (lane & 3)*2;
            size_t base = (size_t)(rowbase + r)*DM + cl;
            float2 q0v = *(const float2*)(g_q + base);
            float2 q1v = *(const float2*)(g_q + base + 8*DM);
            *(float2*)(g_att + base)        = make_float2(acc[mi][ni][0] + q0v.x, acc[mi][ni][1] + q0v.y);
            *(float2*)(g_att + base + 8*DM) = make_float2(acc[mi][ni][2] + q1v.x, acc[mi][ni][3] + q1v.y);
        }
    }
}

// ---------------------------------------------------------------------------
// Kernel 5: LayerNorm + relu, one block (128 thr) per row
// ---------------------------------------------------------------------------
__global__ __launch_bounds__(128) void ln_kernel(const float* __restrict__ lnw,
                                                 const float* __restrict__ lnb,
                                                 float* __restrict__ out){
    const int row = blockIdx.x, tid = threadIdx.x;
    const float4 x = *(const float4*)(g_att + (size_t)row*DM + tid*4);
    float s  = x.x + x.y + x.z + x.w;
    float ss = fmaf(x.x, x.x, fmaf(x.y, x.y, fmaf(x.z, x.z, x.w*x.w)));
    #pragma unroll
    for (int o = 16; o > 0; o >>= 1){
        s  += __shfl_xor_sync(0xffffffffu, s,  o);
        ss += __shfl_xor_sync(0xffffffffu, ss, o);
    }
    __shared__ float red[8];
    int warp = tid >> 5, lane = tid & 31;
    if (lane == 0){ red[warp] = s; red[warp+4] = ss; }
    __syncthreads();
    s  = red[0] + red[1] + red[2] + red[3];
    ss = red[4] + red[5] + red[6] + red[7];
    float mu  = s * (1.0f/DM);
    float inv = rsqrtf(ss * (1.0f/DM) - mu*mu + 1e-5f);
    const float4 w = *(const float4*)(lnw + tid*4);
    const float4 bb = *(const float4*)(lnb + tid*4);
    float4 y;
    y.x = fmaxf((x.x - mu)*inv*w.x + bb.x, 0.f);
    y.y = fmaxf((x.y - mu)*inv*w.y + bb.y, 0.f);
    y.z = fmaxf((x.z - mu)*inv*w.z + bb.z, 0.f);
    y.w = fmaxf((x.w - mu)*inv*w.w + bb.w, 0.f);
    *(float4*)(out + (size_t)row*DM + tid*4) = y;
}

// ---------------------------------------------------------------------------
extern "C" void kernel_launch(void* const* d_in, const int* in_sizes, int n_in,
                              void* d_out, int out_size){
    const float* Q   = (const float*)d_in[0];
    const float* Wq  = (const float*)d_in[1];
    const float* bq  = (const float*)d_in[2];
    const float* Wk  = (const float*)d_in[3];
    const float* bk  = (const float*)d_in[4];
    const float* Wv  = (const float*)d_in[5];
    const float* bv  = (const float*)d_in[6];
    const float* lnw = (const float*)d_in[7];
    const float* lnb = (const float*)d_in[8];
    float* out = (float*)d_out;

    valid_kernel<<<NROWS/8, 256>>>(Q);
    proj_kernel<<<dim3(DM/64, NROWS/128, 3), 256>>>(Q, Wq, bq, Wk, bk, Wv, bv);

    // escore smem: (128*68 + 2*128*68) u32 + 1024 int + 384 f32 = 110080 B
    const int es_smem = (128*SQ_STR + 2*KT_U)*4 + SEQ*4 + 384*4;
    cudaFuncSetAttribute(escore_kernel, cudaFuncAttributeMaxDynamicSharedMemorySize, es_smem);
    escore_kernel<<<dim3(SEQ/128, NH, NB), 256, es_smem>>>(out + OUT0);

    const int wv_smem = (128*SQ_STR + 64*SV_STR) * 4;  // 53248
    cudaFuncSetAttribute(wv_kernel, cudaFuncAttributeMaxDynamicSharedMemorySize, wv_smem);
    wv_kernel<<<dim3(SEQ/128, NH, NB), 256, wv_smem>>>(out + OUT0);

    ln_kernel<<<NROWS, 128>>>(lnw, lnb, out);
}

// round 10
// speedup vs baseline: 1.3304x; 1.0205x over previous
#include <cuda_runtime.h>

#define NB 16
#define SEQ 1024
#define DM 512
#define NH 8
#define HD 64
#define NROWS (NB*SEQ)          // 16384
#define OUT0 (NROWS*DM)         // 8388608 floats: out region, then weights

#define SQ_STR 68               // smem stride for [rows][64] tf32 tiles
#define SV_STR 72               // smem stride for V [k][n] tiles (≡8 mod 32)
#define KT_U   (128*SQ_STR)     // one 128x64 K-tile in uint units

__device__ float    g_q[NROWS*DM];     // fp32 (relu'd) — residual source
__device__ float    g_k[NROWS*DM];     // tf32 bit patterns
__device__ float    g_v[NROWS*DM];     // tf32 bit patterns
__device__ unsigned g_qtf[NROWS*DM];   // tf32 of input Q (proj A operand)
__device__ unsigned g_wt[3*DM*DM];     // tf32 of Wq/Wk/Wv
__device__ float    g_att[NROWS*DM];
__device__ int      g_valid[NROWS];

__device__ __forceinline__ unsigned f2tf(float x){
    unsigned r; asm("cvt.rna.tf32.f32 %0, %1;" : "=r"(r) : "f"(x)); return r;
}
__device__ __forceinline__ uint4 f2tf4(float4 v){
    return make_uint4(f2tf(v.x), f2tf(v.y), f2tf(v.z), f2tf(v.w));
}
__device__ __forceinline__ void cpasync16(unsigned s, const void* g){
    asm volatile("cp.async.cg.shared.global [%0], [%1], 16;" :: "r"(s), "l"(g));
}
#define CP_COMMIT() asm volatile("cp.async.commit_group;")
#define CP_WAIT(n)  asm volatile("cp.async.wait_group %0;" :: "n"(n))

// D += A(16x8 row) * B(8x8 col), tf32 in, fp32 accum
__device__ __forceinline__ void mma8(float c[4], const unsigned a[4], const unsigned b[2]){
    asm volatile("mma.sync.aligned.m16n8k8.row.col.f32.tf32.tf32.f32 "
        "{%0,%1,%2,%3}, {%4,%5,%6,%7}, {%8,%9}, {%0,%1,%2,%3};\n"
        : "+f"(c[0]), "+f"(c[1]), "+f"(c[2]), "+f"(c[3])
        : "r"(a[0]), "r"(a[1]), "r"(a[2]), "r"(a[3]), "r"(b[0]), "r"(b[1]));
}

// ---------------------------------------------------------------------------
// prep_q: validity + Q -> tf32 copy. One warp per row.
// ---------------------------------------------------------------------------
__global__ void prep_q(const float* __restrict__ Q){
    int row  = blockIdx.x * 8 + (threadIdx.x >> 5);
    int lane = threadIdx.x & 31;
    const float4* p = (const float4*)(Q + (size_t)row * DM);
    uint4* o = (uint4*)(g_qtf + (size_t)row * DM);
    bool nz = false;
    #pragma unroll
    for (int i = 0; i < 4; i++){   // 4 float4 x 32 lanes = 512 = full row ✓
        float4 v = p[lane + i*32];
        nz |= (v.x != 0.f) || (v.y != 0.f) || (v.z != 0.f) || (v.w != 0.f);
        o[lane + i*32] = f2tf4(v);
    }
    unsigned m = __ballot_sync(0xffffffffu, nz);
    if (lane == 0) g_valid[row] = (m != 0u);
}

// prep_w: W matrices -> tf32. grid (DM*DM/1024, 3), 256 thr, 1 float4/thread.
__global__ void prep_w(const float* __restrict__ Wq,
                       const float* __restrict__ Wk,
                       const float* __restrict__ Wv){
    const int z = blockIdx.y;
    const float* src = (z==0) ? Wq : (z==1) ? Wk : Wv;
    int idx = blockIdx.x * 256 + threadIdx.x;                 // float4 index
    float4 v = ((const float4*)src)[idx];
    ((uint4*)(g_wt + (size_t)z*DM*DM))[idx] = f2tf4(v);
}

// ---------------------------------------------------------------------------
// proj: out = relu(Q @ W^T + b). Block tile 128x128, BK=32, 3-stage cp.async.
// 8 warps as 4x2, warp tile 32x64. All operands raw tf32 from gmem.
// ---------------------------------------------------------------------------
#define P_STG (128*36*2)        // A[128x36] + B[128x36] per stage (u32)

__global__ __launch_bounds__(256, 2) void proj_kernel(
    const float* __restrict__ bq, const float* __restrict__ bk,
    const float* __restrict__ bv)
{
    extern __shared__ unsigned smem[];
    const int z = blockIdx.z;
    const float* bias = (z==0) ? bq : (z==1) ? bk : bv;
    float*       out  = (z==0) ? g_q : (z==1) ? g_k : g_v;
    const unsigned* gA = g_qtf;
    const unsigned* gB = g_wt + (size_t)z*DM*DM;

    const int m0 = blockIdx.y * 128, n0 = blockIdx.x * 128;
    const int tid = threadIdx.x, warp = tid >> 5, lane = tid & 31;
    const int wm = warp >> 1, wn = warp & 1;
    const unsigned smb = (unsigned)__cvta_generic_to_shared(smem);

    float acc[2][8][4];
    #pragma unroll
    for (int i=0;i<2;i++)
        #pragma unroll
        for (int j=0;j<8;j++)
            #pragma unroll
            for (int r=0;r<4;r++) acc[i][j][r] = 0.f;

    // issue stage: A 1024 + B 1024 16B-chunks = 4+4 per thread ✓
    auto issue = [&](int kt, int buf){
        unsigned base = smb + (unsigned)(buf*P_STG)*4u;
        #pragma unroll
        for (int t = 0; t < 4; t++){
            int idx = tid + t*256, r = idx >> 3, c = (idx & 7) * 4;
            cpasync16(base + (unsigned)(r*36 + c)*4u,
                      gA + (size_t)(m0 + r)*DM + kt*32 + c);
            cpasync16(base + (unsigned)(128*36 + r*36 + c)*4u,
                      gB + (size_t)(n0 + r)*DM + kt*32 + c);
        }
        CP_COMMIT();
    };

    issue(0, 0); issue(1, 1);

    for (int kt = 0; kt < 16; kt++){
        if (kt < 14) CP_WAIT(1); else CP_WAIT(0);
        __syncthreads();
        if (kt + 2 < 16) issue(kt + 2, (kt + 2) % 3);

        const unsigned* As = smem + (kt % 3)*P_STG;
        const unsigned* Bs = As + 128*36;
        #pragma unroll
        for (int ks = 0; ks < 32; ks += 8){
            const int cb = ks + (lane & 3);
            unsigned a[2][4];
            #pragma unroll
            for (int mi = 0; mi < 2; mi++){
                int r0 = wm*32 + mi*16 + (lane >> 2);
                a[mi][0] = As[ r0   *36 + cb];
                a[mi][1] = As[(r0+8)*36 + cb];
                a[mi][2] = As[ r0   *36 + cb + 4];
                a[mi][3] = As[(r0+8)*36 + cb + 4];
            }
            #pragma unroll
            for (int ni = 0; ni < 8; ni++){
                int c0 = wn*64 + ni*8 + (lane >> 2);
                unsigned bf[2] = { Bs[c0*36 + cb], Bs[c0*36 + cb + 4] };
                mma8(acc[0][ni], a[0], bf);
                mma8(acc[1][ni], a[1], bf);
            }
        }
        __syncthreads();   // stage (kt%3) free for kt+3's issue next iter
    }

    #pragma unroll
    for (int mi = 0; mi < 2; mi++){
        #pragma unroll
        for (int ni = 0; ni < 8; ni++){
            int row = m0 + wm*32 + mi*16 + (lane >> 2);
            int col = n0 + wn*64 + ni*8 + (lane & 3)*2;
            float b0 = __ldg(bias + col), b1 = __ldg(bias + col + 1);
            float v00 = fmaxf(acc[mi][ni][0] + b0, 0.f), v01 = fmaxf(acc[mi][ni][1] + b1, 0.f);
            float v10 = fmaxf(acc[mi][ni][2] + b0, 0.f), v11 = fmaxf(acc[mi][ni][3] + b1, 0.f);
            if (z != 0){  // k/v: store tf32 bit patterns
                v00 = __uint_as_float(f2tf(v00)); v01 = __uint_as_float(f2tf(v01));
                v10 = __uint_as_float(f2tf(v10)); v11 = __uint_as_float(f2tf(v11));
            }
            *(float2*)(out + (size_t)row*DM + col)     = make_float2(v00, v01);
            *(float2*)(out + (size_t)(row+8)*DM + col) = make_float2(v10, v11);
        }
    }
}

// ---------------------------------------------------------------------------
// escore — no-max softmax, two streaming passes over K (R9-proven).
// pass 1 writes weights as rna-tf32 bit patterns (wv reads them raw).
// ---------------------------------------------------------------------------
__global__ __launch_bounds__(256, 2) void escore_kernel(float* __restrict__ wout){
    extern __shared__ unsigned smem[];
    unsigned* sQ   = smem;                   // 128*68
    unsigned* sK   = sQ + 128*SQ_STR;        // 2 * 128*68
    int*      sVK  = (int*)(sK + 2*KT_U);    // 1024
    float*    sRS2 = (float*)(sVK + SEQ);    // 256
    float*    sRS  = sRS2 + 256;             // 128

    const int b = blockIdx.z, h = blockIdx.y;
    const int q0 = blockIdx.x * 128;
    const int tid = threadIdx.x, warp = tid >> 5, lane = tid & 31;
    const int wm = warp >> 1, wn = warp & 1;
    const int rowbase = b * SEQ;

    #pragma unroll
    for (int t = 0; t < 8; t++){   // 128x64 = 2048 float4 = 8 x 256 ✓
        int idx = tid + t*256, r = idx >> 4, c = (idx & 15) * 4;
        float4 v = *(const float4*)(g_q + (size_t)(rowbase + q0 + r)*DM + h*HD + c);
        *(uint4*)&sQ[r*SQ_STR + c] = f2tf4(v);
    }
    for (int i = tid; i < SEQ; i += 256) sVK[i] = g_valid[rowbase + i];
    __syncthreads();

    bool vqa[4];
    #pragma unroll
    for (int j = 0; j < 4; j++)
        vqa[j] = sVK[q0 + wm*32 + (j>>1)*16 + (j&1)*8 + (lane>>2)] != 0;

    const unsigned skb = (unsigned)__cvta_generic_to_shared(sK);
    const float* gK = g_k + (size_t)rowbase*DM + h*HD;

    #pragma unroll
    for (int t2 = 0; t2 < 8; t2++){
        int idx = tid + t2*256, r = idx >> 4, c = (idx & 15) * 4;
        cpasync16(skb + ((unsigned)(r*SQ_STR + c))*4u, gK + (size_t)r*DM + c);
    }
    CP_COMMIT();

    float rsum[4] = {0.f, 0.f, 0.f, 0.f};
    float rs[4]   = {0.f, 0.f, 0.f, 0.f};

    #pragma unroll 1
    for (int pass = 0; pass < 2; pass++){
        #pragma unroll 1
        for (int kt = 0; kt < 8; kt++){
            const int tc = pass*8 + kt;
            const unsigned* sKc = sK + (tc & 1)*KT_U;
            if (tc < 15){
                const int nk = (tc + 1) & 7;
                const unsigned nb = skb + (unsigned)(((tc+1) & 1)*KT_U)*4u;
                #pragma unroll
                for (int t2 = 0; t2 < 8; t2++){
                    int idx = tid + t2*256, r = idx >> 4, c = (idx & 15) * 4;
                    cpasync16(nb + ((unsigned)(r*SQ_STR + c))*4u,
                              gK + (size_t)(nk*128 + r)*DM + c);
                }
                CP_COMMIT();
                CP_WAIT(1);
            } else {
                CP_WAIT(0);
            }
            __syncthreads();

            float acc[2][8][4];
            #pragma unroll
            for (int i=0;i<2;i++)
                #pragma unroll
                for (int j=0;j<8;j++)
                    #pragma unroll
                    for (int r=0;r<4;r++) acc[i][j][r] = 0.f;

            #pragma unroll
            for (int ks = 0; ks < 64; ks += 8){
                const int cb = ks + (lane & 3);
                unsigned a[2][4];
                #pragma unroll
                for (int mi = 0; mi < 2; mi++){
                    int r0 = wm*32 + mi*16 + (lane >> 2);
                    a[mi][0] = sQ[ r0   *SQ_STR + cb];
                    a[mi][1] = sQ[(r0+8)*SQ_STR + cb];
                    a[mi][2] = sQ[ r0   *SQ_STR + cb + 4];
                    a[mi][3] = sQ[(r0+8)*SQ_STR + cb + 4];
                }
                #pragma unroll
                for (int ni = 0; ni < 8; ni++){
                    int c0 = wn*64 + ni*8 + (lane >> 2);
                    unsigned bf[2] = { sKc[c0*SQ_STR + cb], sKc[c0*SQ_STR + cb + 4] };
                    mma8(acc[0][ni], a[0], bf);
                    mma8(acc[1][ni], a[1], bf);
                }
            }

            #pragma unroll
            for (int mi = 0; mi < 2; mi++){
                #pragma unroll
                for (int ni = 0; ni < 8; ni++){
                    const int cl = kt*128 + wn*64 + ni*8 + (lane & 3)*2;
                    const bool v0 = sVK[cl] != 0, v1 = sVK[cl+1] != 0;
                    float e0 = (vqa[mi*2  ] && v0) ? __expf(acc[mi][ni][0]*0.125f) : 0.f;
                    float e1 = (vqa[mi*2  ] && v1) ? __expf(acc[mi][ni][1]*0.125f) : 0.f;
                    float e2 = (vqa[mi*2+1] && v0) ? __expf(acc[mi][ni][2]*0.125f) : 0.f;
                    float e3 = (vqa[mi*2+1] && v1) ? __expf(acc[mi][ni][3]*0.125f) : 0.f;
                    if (pass == 0){
                        rsum[mi*2  ] += e0 + e1;
                        rsum[mi*2+1] += e2 + e3;
                    } else {
                        size_t rg = (size_t)((b*NH + h)*SEQ + q0 + wm*32 + mi*16 + (lane>>2));
                        *(float2*)(wout + rg*SEQ + cl) = make_float2(
                            __uint_as_float(f2tf(e0*rs[mi*2])),
                            __uint_as_float(f2tf(e1*rs[mi*2])));
                        *(float2*)(wout + (rg+8)*SEQ + cl) = make_float2(
                            __uint_as_float(f2tf(e2*rs[mi*2+1])),
                            __uint_as_float(f2tf(e3*rs[mi*2+1])));
                    }
                }
            }
            __syncthreads();
        }

        if (pass == 0){
            #pragma unroll
            for (int j = 0; j < 4; j++){
                rsum[j] += __shfl_xor_sync(0xffffffffu, rsum[j], 1);
                rsum[j] += __shfl_xor_sync(0xffffffffu, rsum[j], 2);
            }
            if ((lane & 3) == 0){
                #pragma unroll
                for (int j = 0; j < 4; j++){
                    int row = wm*32 + (j>>1)*16 + (j&1)*8 + (lane>>2);
                    sRS2[wn*128 + row] = rsum[j];
                }
            }
            __syncthreads();
            if (tid < 128){
                float s = sRS2[tid] + sRS2[128 + tid];
                sRS[tid] = (s > 0.f) ? (1.f / s) : 0.f;
            }
            __syncthreads();
            #pragma unroll
            for (int j = 0; j < 4; j++)
                rs[j] = sRS[wm*32 + (j>>1)*16 + (j&1)*8 + (lane>>2)];
        }
    }
}

// ---------------------------------------------------------------------------
// wv: attn = W @ V + residual. W (tf32 bits) and V (tf32 bits) streamed raw
// via 3-stage cp.async, k-tile 32. Block 128x64, 8 warps 4x2, warp 32x32.
// ---------------------------------------------------------------------------
#define WV_STG (128*36 + 32*SV_STR)   // W[128x36] + V[32x72] per stage (u32)

__global__ __launch_bounds__(256) void wv_kernel(const float* __restrict__ wout){
    extern __shared__ unsigned smem[];
    const int b = blockIdx.z, h = blockIdx.y;
    const int m0 = blockIdx.x * 128;
    const int tid = threadIdx.x, warp = tid >> 5, lane = tid & 31;
    const int rowbase = b * SEQ;
    const int wm = warp >> 1, wn = warp & 1;
    const unsigned* Wg = (const unsigned*)wout + (size_t)((b*NH + h)*SEQ + m0) * SEQ;
    const float* gV = g_v + (size_t)rowbase*DM + h*HD;
    const unsigned smb = (unsigned)__cvta_generic_to_shared(smem);

    float acc[2][4][4];
    #pragma unroll
    for (int i=0;i<2;i++)
        #pragma unroll
        for (int j=0;j<4;j++)
            #pragma unroll
            for (int r=0;r<4;r++) acc[i][j][r] = 0.f;

    // issue: W 128x32 = 1024 chunks (4/thr), V 32x64 = 512 chunks (2/thr) ✓
    auto issue = [&](int kt, int buf){
        unsigned base = smb + (unsigned)(buf*WV_STG)*4u;
        #pragma unroll
        for (int t = 0; t < 4; t++){
            int idx = tid + t*256, r = idx >> 3, c = (idx & 7) * 4;
            cpasync16(base + (unsigned)(r*36 + c)*4u,
                      Wg + (size_t)r*SEQ + kt*32 + c);
        }
        #pragma unroll
        for (int t = 0; t < 2; t++){
            int idx = tid + t*256, r = idx >> 4, c = (idx & 15) * 4;
            cpasync16(base + (unsigned)(128*36 + r*SV_STR + c)*4u,
                      gV + (size_t)(kt*32 + r)*DM + c);
        }
        CP_COMMIT();
    };

    issue(0, 0); issue(1, 1);

    for (int kt = 0; kt < 32; kt++){
        if (kt < 30) CP_WAIT(1); else CP_WAIT(0);
        __syncthreads();
        if (kt + 2 < 32) issue(kt + 2, (kt + 2) % 3);

        const unsigned* sW = smem + (kt % 3)*WV_STG;
        const unsigned* sV = sW + 128*36;
        #pragma unroll
        for (int ks = 0; ks < 32; ks += 8){
            const int cb = ks + (lane & 3);
            unsigned a[2][4];
            #pragma unroll
            for (int mi = 0; mi < 2; mi++){
                int r0 = wm*32 + mi*16 + (lane >> 2);
                a[mi][0] = sW[ r0   *36 + cb];
                a[mi][1] = sW[(r0+8)*36 + cb];
                a[mi][2] = sW[ r0   *36 + cb + 4];
                a[mi][3] = sW[(r0+8)*36 + cb + 4];
            }
            #pragma unroll
            for (int ni = 0; ni < 4; ni++){
                int c0 = wn*32 + ni*8 + (lane >> 2);
                unsigned bf[2] = { sV[cb*SV_STR + c0], sV[(cb+4)*SV_STR + c0] };
                mma8(acc[0][ni], a[0], bf);
                mma8(acc[1][ni], a[1], bf);
            }
        }
        __syncthreads();
    }

    #pragma unroll
    for (int mi = 0; mi < 2; mi++){
        #pragma unroll
        for (int ni = 0; ni < 4; ni++){
            int r  = m0 + wm*32 + mi*16 + (lane >> 2);
            int cl = h*HD + wn*32 + ni*8 + (lane & 3)*2;
            size_t base = (size_t)(rowbase + r)*DM + cl;
            float2 q0v = *(const float2*)(g_q + base);
            float2 q1v = *(const float2*)(g_q + base + 8*DM);
            *(float2*)(g_att + base)        = make_float2(acc[mi][ni][0] + q0v.x, acc[mi][ni][1] + q0v.y);
            *(float2*)(g_att + base + 8*DM) = make_float2(acc[mi][ni][2] + q1v.x, acc[mi][ni][3] + q1v.y);
        }
    }
}

// ---------------------------------------------------------------------------
// ln: LayerNorm + relu, one block (128 thr) per row
// ---------------------------------------------------------------------------
__global__ __launch_bounds__(128) void ln_kernel(const float* __restrict__ lnw,
                                                 const float* __restrict__ lnb,
                                                 float* __restrict__ out){
    const int row = blockIdx.x, tid = threadIdx.x;
    const float4 x = *(const float4*)(g_att + (size_t)row*DM + tid*4);
    float s  = x.x + x.y + x.z + x.w;
    float ss = fmaf(x.x, x.x, fmaf(x.y, x.y, fmaf(x.z, x.z, x.w*x.w)));
    #pragma unroll
    for (int o = 16; o > 0; o >>= 1){
        s  += __shfl_xor_sync(0xffffffffu, s,  o);
        ss += __shfl_xor_sync(0xffffffffu, ss, o);
    }
    __shared__ float red[8];
    int warp = tid >> 5, lane = tid & 31;
    if (lane == 0){ red[warp] = s; red[warp+4] = ss; }
    __syncthreads();
    s  = red[0] + red[1] + red[2] + red[3];
    ss = red[4] + red[5] + red[6] + red[7];
    float mu  = s * (1.0f/DM);
    float inv = rsqrtf(ss * (1.0f/DM) - mu*mu + 1e-5f);
    const float4 w = *(const float4*)(lnw + tid*4);
    const float4 bb = *(const float4*)(lnb + tid*4);
    float4 y;
    y.x = fmaxf((x.x - mu)*inv*w.x + bb.x, 0.f);
    y.y = fmaxf((x.y - mu)*inv*w.y + bb.y, 0.f);
    y.z = fmaxf((x.z - mu)*inv*w.z + bb.z, 0.f);
    y.w = fmaxf((x.w - mu)*inv*w.w + bb.w, 0.f);
    *(float4*)(out + (size_t)row*DM + tid*4) = y;
}

// ---------------------------------------------------------------------------
extern "C" void kernel_launch(void* const* d_in, const int* in_sizes, int n_in,
                              void* d_out, int out_size){
    const float* Q   = (const float*)d_in[0];
    const float* Wq  = (const float*)d_in[1];
    const float* bq  = (const float*)d_in[2];
    const float* Wk  = (const float*)d_in[3];
    const float* bk  = (const float*)d_in[4];
    const float* Wv  = (const float*)d_in[5];
    const float* bv  = (const float*)d_in[6];
    const float* lnw = (const float*)d_in[7];
    const float* lnb = (const float*)d_in[8];
    float* out = (float*)d_out;

    prep_q<<<NROWS/8, 256>>>(Q);
    prep_w<<<dim3(DM*DM/1024, 3), 256>>>(Wq, Wk, Wv);

    const int pj_smem = 3 * P_STG * 4;   // 110592
    cudaFuncSetAttribute(proj_kernel, cudaFuncAttributeMaxDynamicSharedMemorySize, pj_smem);
    proj_kernel<<<dim3(DM/128, NROWS/128, 3), 256, pj_smem>>>(bq, bk, bv);

    const int es_smem = (128*SQ_STR + 2*KT_U)*4 + SEQ*4 + 384*4;  // 110080
    cudaFuncSetAttribute(escore_kernel, cudaFuncAttributeMaxDynamicSharedMemorySize, es_smem);
    escore_kernel<<<dim3(SEQ/128, NH, NB), 256, es_smem>>>(out + OUT0);

    const int wv_smem = 3 * WV_STG * 4;  // 82944
    cudaFuncSetAttribute(wv_kernel, cudaFuncAttributeMaxDynamicSharedMemorySize, wv_smem);
    wv_kernel<<<dim3(SEQ/128, NH, NB), 256, wv_smem>>>(out + OUT0);

    ln_kernel<<<NROWS, 128>>>(lnw, lnb, out);
}

// round 11
// speedup vs baseline: 1.4482x; 1.0885x over previous
#include <cuda_runtime.h>

#define NB 16
#define SEQ 1024
#define DM 512
#define NH 8
#define HD 64
#define NROWS (NB*SEQ)          // 16384
#define OUT0 (NROWS*DM)         // 8388608 floats: out region, then weights

#define SQ_STR 68               // smem stride for [rows][64] tf32 tiles
#define SV_STR 72               // smem stride for V [k][n] tiles (≡8 mod 32)
#define KT_U   (128*SQ_STR)     // one 128x64 K-tile in uint units

__device__ float    g_q[NROWS*DM];     // fp32 (relu'd) — residual source
__device__ float    g_k[NROWS*DM];     // tf32 bit patterns
__device__ float    g_v[NROWS*DM];     // tf32 bit patterns
__device__ unsigned g_qtf[NROWS*DM];   // tf32 of input Q (proj A operand)
__device__ unsigned g_wt[3*DM*DM];     // tf32 of Wq/Wk/Wv
__device__ float    g_att[NROWS*DM];
__device__ int      g_valid[NROWS];

#define SCALE_L2E 0.18033688011112042f   // 0.125 * log2(e)
#define NEGINF __int_as_float(0xff800000)

__device__ __forceinline__ unsigned f2tf(float x){
    unsigned r; asm("cvt.rna.tf32.f32 %0, %1;" : "=r"(r) : "f"(x)); return r;
}
__device__ __forceinline__ uint4 f2tf4(float4 v){
    return make_uint4(f2tf(v.x), f2tf(v.y), f2tf(v.z), f2tf(v.w));
}
__device__ __forceinline__ float ex2(float x){
    float y; asm("ex2.approx.f32 %0, %1;" : "=f"(y) : "f"(x)); return y;
}
__device__ __forceinline__ void cpasync16(unsigned s, const void* g){
    asm volatile("cp.async.cg.shared.global [%0], [%1], 16;" :: "r"(s), "l"(g));
}
#define CP_COMMIT() asm volatile("cp.async.commit_group;")
#define CP_WAIT(n)  asm volatile("cp.async.wait_group %0;" :: "n"(n))

// D += A(16x8 row) * B(8x8 col), tf32 in, fp32 accum
__device__ __forceinline__ void mma8(float c[4], const unsigned a[4], const unsigned b[2]){
    asm volatile("mma.sync.aligned.m16n8k8.row.col.f32.tf32.tf32.f32 "
        "{%0,%1,%2,%3}, {%4,%5,%6,%7}, {%8,%9}, {%0,%1,%2,%3};\n"
        : "+f"(c[0]), "+f"(c[1]), "+f"(c[2]), "+f"(c[3])
        : "r"(a[0]), "r"(a[1]), "r"(a[2]), "r"(a[3]), "r"(b[0]), "r"(b[1]));
}

// ---------------------------------------------------------------------------
// prep_q: validity + Q -> tf32 copy. One warp per row.
// ---------------------------------------------------------------------------
__global__ void prep_q(const float* __restrict__ Q){
    int row  = blockIdx.x * 8 + (threadIdx.x >> 5);
    int lane = threadIdx.x & 31;
    const float4* p = (const float4*)(Q + (size_t)row * DM);
    uint4* o = (uint4*)(g_qtf + (size_t)row * DM);
    bool nz = false;
    #pragma unroll
    for (int i = 0; i < 4; i++){   // 4 float4 x 32 lanes = 512 = full row ✓
        float4 v = p[lane + i*32];
        nz |= (v.x != 0.f) || (v.y != 0.f) || (v.z != 0.f) || (v.w != 0.f);
        o[lane + i*32] = f2tf4(v);
    }
    unsigned m = __ballot_sync(0xffffffffu, nz);
    if (lane == 0) g_valid[row] = (m != 0u);
}

// prep_w: W matrices -> tf32. grid (DM*DM/1024, 3), 256 thr, 1 float4/thread.
__global__ void prep_w(const float* __restrict__ Wq,
                       const float* __restrict__ Wk,
                       const float* __restrict__ Wv){
    const int z = blockIdx.y;
    const float* src = (z==0) ? Wq : (z==1) ? Wk : Wv;
    int idx = blockIdx.x * 256 + threadIdx.x;                 // float4 index
    float4 v = ((const float4*)src)[idx];
    ((uint4*)(g_wt + (size_t)z*DM*DM))[idx] = f2tf4(v);
}

// ---------------------------------------------------------------------------
// proj: out = relu(Q @ W^T + b). Block tile 128x128, BK=32, 3-stage cp.async.
// 8 warps as 4x2, warp tile 32x64. All operands raw tf32 from gmem.
// ---------------------------------------------------------------------------
#define P_STG (128*36*2)        // A[128x36] + B[128x36] per stage (u32)

__global__ __launch_bounds__(256, 2) void proj_kernel(
    const float* __restrict__ bq, const float* __restrict__ bk,
    const float* __restrict__ bv)
{
    extern __shared__ unsigned smem[];
    const int z = blockIdx.z;
    const float* bias = (z==0) ? bq : (z==1) ? bk : bv;
    float*       out  = (z==0) ? g_q : (z==1) ? g_k : g_v;
    const unsigned* gA = g_qtf;
    const unsigned* gB = g_wt + (size_t)z*DM*DM;

    const int m0 = blockIdx.y * 128, n0 = blockIdx.x * 128;
    const int tid = threadIdx.x, warp = tid >> 5, lane = tid & 31;
    const int wm = warp >> 1, wn = warp & 1;
    const unsigned smb = (unsigned)__cvta_generic_to_shared(smem);

    float acc[2][8][4];
    #pragma unroll
    for (int i=0;i<2;i++)
        #pragma unroll
        for (int j=0;j<8;j++)
            #pragma unroll
            for (int r=0;r<4;r++) acc[i][j][r] = 0.f;

    // issue stage: A 1024 + B 1024 16B-chunks = 4+4 per thread ✓
    auto issue = [&](int kt, int buf){
        unsigned base = smb + (unsigned)(buf*P_STG)*4u;
        #pragma unroll
        for (int t = 0; t < 4; t++){
            int idx = tid + t*256, r = idx >> 3, c = (idx & 7) * 4;
            cpasync16(base + (unsigned)(r*36 + c)*4u,
                      gA + (size_t)(m0 + r)*DM + kt*32 + c);
            cpasync16(base + (unsigned)(128*36 + r*36 + c)*4u,
                      gB + (size_t)(n0 + r)*DM + kt*32 + c);
        }
        CP_COMMIT();
    };

    issue(0, 0); issue(1, 1);

    for (int kt = 0; kt < 16; kt++){
        if (kt < 14) CP_WAIT(1); else CP_WAIT(0);
        __syncthreads();
        if (kt + 2 < 16) issue(kt + 2, (kt + 2) % 3);

        const unsigned* As = smem + (kt % 3)*P_STG;
        const unsigned* Bs = As + 128*36;
        #pragma unroll
        for (int ks = 0; ks < 32; ks += 8){
            const int cb = ks + (lane & 3);
            unsigned a[2][4];
            #pragma unroll
            for (int mi = 0; mi < 2; mi++){
                int r0 = wm*32 + mi*16 + (lane >> 2);
                a[mi][0] = As[ r0   *36 + cb];
                a[mi][1] = As[(r0+8)*36 + cb];
                a[mi][2] = As[ r0   *36 + cb + 4];
                a[mi][3] = As[(r0+8)*36 + cb + 4];
            }
            #pragma unroll
            for (int ni = 0; ni < 8; ni++){
                int c0 = wn*64 + ni*8 + (lane >> 2);
                unsigned bf[2] = { Bs[c0*36 + cb], Bs[c0*36 + cb + 4] };
                mma8(acc[0][ni], a[0], bf);
                mma8(acc[1][ni], a[1], bf);
            }
        }
        __syncthreads();   // stage (kt%3) free for kt+3's issue next iter
    }

    #pragma unroll
    for (int mi = 0; mi < 2; mi++){
        #pragma unroll
        for (int ni = 0; ni < 8; ni++){
            int row = m0 + wm*32 + mi*16 + (lane >> 2);
            int col = n0 + wn*64 + ni*8 + (lane & 3)*2;
            float b0 = __ldg(bias + col), b1 = __ldg(bias + col + 1);
            float v00 = fmaxf(acc[mi][ni][0] + b0, 0.f), v01 = fmaxf(acc[mi][ni][1] + b1, 0.f);
            float v10 = fmaxf(acc[mi][ni][2] + b0, 0.f), v11 = fmaxf(acc[mi][ni][3] + b1, 0.f);
            if (z != 0){  // k/v: store tf32 bit patterns
                v00 = __uint_as_float(f2tf(v00)); v01 = __uint_as_float(f2tf(v01));
                v10 = __uint_as_float(f2tf(v10)); v11 = __uint_as_float(f2tf(v11));
            }
            *(float2*)(out + (size_t)row*DM + col)     = make_float2(v00, v01);
            *(float2*)(out + (size_t)(row+8)*DM + col) = make_float2(v10, v11);
        }
    }
}

// ---------------------------------------------------------------------------
// escore — no-max softmax via exp2, two streaming passes over K.
// Q pre-scaled by 0.125*log2(e) so weight = ex2(acc + kbias), kbias ∈ {0,-inf}
// (additive k-mask; q-mask folded into rs). pass 1 writes plain fp32
// normalized weights (wv's mma truncates fp32->tf32 in HW).
// ---------------------------------------------------------------------------
__global__ __launch_bounds__(256, 2) void escore_kernel(float* __restrict__ wout){
    extern __shared__ unsigned smem[];
    unsigned* sQ   = smem;                   // 128*68
    unsigned* sK   = sQ + 128*SQ_STR;        // 2 * 128*68
    float*    kb   = (float*)(sK + 2*KT_U);  // 1024: 0 or -inf per k column
    float*    sRS2 = kb + SEQ;               // 256
    float*    sRS  = sRS2 + 256;             // 128

    const int b = blockIdx.z, h = blockIdx.y;
    const int q0 = blockIdx.x * 128;
    const int tid = threadIdx.x, warp = tid >> 5, lane = tid & 31;
    const int wm = warp >> 1, wn = warp & 1;
    const int rowbase = b * SEQ;

    #pragma unroll
    for (int t = 0; t < 8; t++){   // 128x64 = 2048 float4 = 8 x 256 ✓
        int idx = tid + t*256, r = idx >> 4, c = (idx & 15) * 4;
        float4 v = *(const float4*)(g_q + (size_t)(rowbase + q0 + r)*DM + h*HD + c);
        v.x *= SCALE_L2E; v.y *= SCALE_L2E; v.z *= SCALE_L2E; v.w *= SCALE_L2E;
        *(uint4*)&sQ[r*SQ_STR + c] = f2tf4(v);
    }
    for (int i = tid; i < SEQ; i += 256)
        kb[i] = g_valid[rowbase + i] ? 0.f : NEGINF;
    __syncthreads();

    const unsigned skb = (unsigned)__cvta_generic_to_shared(sK);
    const float* gK = g_k + (size_t)rowbase*DM + h*HD;

    #pragma unroll
    for (int t2 = 0; t2 < 8; t2++){   // 128x64 = 2048 float4 = 8 x 256 ✓
        int idx = tid + t2*256, r = idx >> 4, c = (idx & 15) * 4;
        cpasync16(skb + ((unsigned)(r*SQ_STR + c))*4u, gK + (size_t)r*DM + c);
    }
    CP_COMMIT();

    float rsum[4] = {0.f, 0.f, 0.f, 0.f};
    float rs[4]   = {0.f, 0.f, 0.f, 0.f};

    #pragma unroll 1
    for (int pass = 0; pass < 2; pass++){
        #pragma unroll 1
        for (int kt = 0; kt < 8; kt++){
            const int tc = pass*8 + kt;
            const unsigned* sKc = sK + (tc & 1)*KT_U;
            if (tc < 15){
                const int nk = (tc + 1) & 7;
                const unsigned nb = skb + (unsigned)(((tc+1) & 1)*KT_U)*4u;
                #pragma unroll
                for (int t2 = 0; t2 < 8; t2++){
                    int idx = tid + t2*256, r = idx >> 4, c = (idx & 15) * 4;
                    cpasync16(nb + ((unsigned)(r*SQ_STR + c))*4u,
                              gK + (size_t)(nk*128 + r)*DM + c);
                }
                CP_COMMIT();
                CP_WAIT(1);
            } else {
                CP_WAIT(0);
            }
            __syncthreads();

            float acc[2][8][4];
            #pragma unroll
            for (int i=0;i<2;i++)
                #pragma unroll
                for (int j=0;j<8;j++)
                    #pragma unroll
                    for (int r=0;r<4;r++) acc[i][j][r] = 0.f;

            #pragma unroll
            for (int ks = 0; ks < 64; ks += 8){
                const int cb = ks + (lane & 3);
                unsigned a[2][4];
                #pragma unroll
                for (int mi = 0; mi < 2; mi++){
                    int r0 = wm*32 + mi*16 + (lane >> 2);
                    a[mi][0] = sQ[ r0   *SQ_STR + cb];
                    a[mi][1] = sQ[(r0+8)*SQ_STR + cb];
                    a[mi][2] = sQ[ r0   *SQ_STR + cb + 4];
                    a[mi][3] = sQ[(r0+8)*SQ_STR + cb + 4];
                }
                #pragma unroll
                for (int ni = 0; ni < 8; ni++){
                    int c0 = wn*64 + ni*8 + (lane >> 2);
                    unsigned bf[2] = { sKc[c0*SQ_STR + cb], sKc[c0*SQ_STR + cb + 4] };
                    mma8(acc[0][ni], a[0], bf);
                    mma8(acc[1][ni], a[1], bf);
                }
            }

            // epilogue: e = ex2(acc + kbias); rowsum (pass0) / store (pass1)
            #pragma unroll
            for (int ni = 0; ni < 8; ni++){
                const int cl = kt*128 + wn*64 + ni*8 + (lane & 3)*2;
                const float2 kb2 = *(const float2*)&kb[cl];
                float e0 = ex2(acc[0][ni][0] + kb2.x);
                float e1 = ex2(acc[0][ni][1] + kb2.y);
                float e2 = ex2(acc[0][ni][2] + kb2.x);
                float e3 = ex2(acc[0][ni][3] + kb2.y);
                float e4 = ex2(acc[1][ni][0] + kb2.x);
                float e5 = ex2(acc[1][ni][1] + kb2.y);
                float e6 = ex2(acc[1][ni][2] + kb2.x);
                float e7 = ex2(acc[1][ni][3] + kb2.y);
                if (pass == 0){
                    rsum[0] += e0 + e1;
                    rsum[1] += e2 + e3;
                    rsum[2] += e4 + e5;
                    rsum[3] += e6 + e7;
                } else {
                    size_t rg = (size_t)((b*NH + h)*SEQ + q0 + wm*32 + (lane>>2));
                    *(float2*)(wout + rg*SEQ + cl)      = make_float2(e0*rs[0], e1*rs[0]);
                    *(float2*)(wout + (rg+ 8)*SEQ + cl) = make_float2(e2*rs[1], e3*rs[1]);
                    *(float2*)(wout + (rg+16)*SEQ + cl) = make_float2(e4*rs[2], e5*rs[2]);
                    *(float2*)(wout + (rg+24)*SEQ + cl) = make_float2(e6*rs[3], e7*rs[3]);
                }
            }
            __syncthreads();
        }

        if (pass == 0){
            // quad-reduce (n halves within quad), then combine the 2 n-warps
            #pragma unroll
            for (int j = 0; j < 4; j++){
                rsum[j] += __shfl_xor_sync(0xffffffffu, rsum[j], 1);
                rsum[j] += __shfl_xor_sync(0xffffffffu, rsum[j], 2);
            }
            if ((lane & 3) == 0){
                #pragma unroll
                for (int j = 0; j < 4; j++){
                    int row = wm*32 + j*8 + (lane>>2);
                    sRS2[wn*128 + row] = rsum[j];
                }
            }
            __syncthreads();
            if (tid < 128){
                float s = sRS2[tid] + sRS2[128 + tid];
                bool vq = g_valid[rowbase + q0 + tid] != 0;
                sRS[tid] = (vq && s > 0.f) ? (1.f / s) : 0.f;  // invalid q -> 0
            }
            __syncthreads();
            #pragma unroll
            for (int j = 0; j < 4; j++)
                rs[j] = sRS[wm*32 + j*8 + (lane>>2)];
        }
    }
}

// ---------------------------------------------------------------------------
// wv: attn = W @ V + residual. W (fp32, HW-truncated to tf32) and V (tf32)
// streamed raw via 3-stage cp.async, k-tile 32. Block 128x64, 8 warps 4x2.
// ---------------------------------------------------------------------------
#define WV_STG (128*36 + 32*SV_STR)   // W[128x36] + V[32x72] per stage (u32)

__global__ __launch_bounds__(256) void wv_kernel(const float* __restrict__ wout){
    extern __shared__ unsigned smem[];
    const int b = blockIdx.z, h = blockIdx.y;
    const int m0 = blockIdx.x * 128;
    const int tid = threadIdx.x, warp = tid >> 5, lane = tid & 31;
    const int rowbase = b * SEQ;
    const int wm = warp >> 1, wn = warp & 1;
    const unsigned* Wg = (const unsigned*)wout + (size_t)((b*NH + h)*SEQ + m0) * SEQ;
    const float* gV = g_v + (size_t)rowbase*DM + h*HD;
    const unsigned smb = (unsigned)__cvta_generic_to_shared(smem);

    float acc[2][4][4];
    #pragma unroll
    for (int i=0;i<2;i++)
        #pragma unroll
        for (int j=0;j<4;j++)
            #pragma unroll
            for (int r=0;r<4;r++) acc[i][j][r] = 0.f;

    // issue: W 128x32 = 1024 chunks (4/thr), V 32x64 = 512 chunks (2/thr) ✓
    auto issue = [&](int kt, int buf){
        unsigned base = smb + (unsigned)(buf*WV_STG)*4u;
        #pragma unroll
        for (int t = 0; t < 4; t++){
            int idx = tid + t*256, r = idx >> 3, c = (idx & 7) * 4;
            cpasync16(base + (unsigned)(r*36 + c)*4u,
                      Wg + (size_t)r*SEQ + kt*32 + c);
        }
        #pragma unroll
        for (int t = 0; t < 2; t++){
            int idx = tid + t*256, r = idx >> 4, c = (idx & 15) * 4;
            cpasync16(base + (unsigned)(128*36 + r*SV_STR + c)*4u,
                      gV + (size_t)(kt*32 + r)*DM + c);
        }
        CP_COMMIT();
    };

    issue(0, 0); issue(1, 1);

    for (int kt = 0; kt < 32; kt++){
        if (kt < 30) CP_WAIT(1); else CP_WAIT(0);
        __syncthreads();
        if (kt + 2 < 32) issue(kt + 2, (kt + 2) % 3);

        const unsigned* sW = smem + (kt % 3)*WV_STG;
        const unsigned* sV = sW + 128*36;
        #pragma unroll
        for (int ks = 0; ks < 32; ks += 8){
            const int cb = ks + (lane & 3);
            unsigned a[2][4];
            #pragma unroll
            for (int mi = 0; mi < 2; mi++){
                int r0 = wm*32 + mi*16 + (lane >> 2);
                a[mi][0] = sW[ r0   *36 + cb];
                a[mi][1] = sW[(r0+8)*36 + cb];
                a[mi][2] = sW[ r0   *36 + cb + 4];
                a[mi][3] = sW[(r0+8)*36 + cb + 4];
            }
            #pragma unroll
            for (int ni = 0; ni < 4; ni++){
                int c0 = wn*32 + ni*8 + (lane >> 2);
                unsigned bf[2] = { sV[cb*SV_STR + c0], sV[(cb+4)*SV_STR + c0] };
                mma8(acc[0][ni], a[0], bf);
                mma8(acc[1][ni], a[1], bf);
            }
        }
        __syncthreads();
    }

    #pragma unroll
    for (int mi = 0; mi < 2; mi++){
        #pragma unroll
        for (int ni = 0; ni < 4; ni++){
            int r  = m0 + wm*32 + mi*16 + (lane >> 2);
            int cl = h*HD + wn*32 + ni*8 + (lane & 3)*2;
            size_t base = (size_t)(rowbase + r)*DM + cl;
            float2 q0v = *(const float2*)(g_q + base);
            float2 q1v = *(const float2*)(g_q + base + 8*DM);
            *(float2*)(g_att + base)        = make_float2(acc[mi][ni][0] + q0v.x, acc[mi][ni][1] + q0v.y);
            *(float2*)(g_att + base + 8*DM) = make_float2(acc[mi][ni][2] + q1v.x, acc[mi][ni][3] + q1v.y);
        }
    }
}

// ---------------------------------------------------------------------------
// ln: LayerNorm + relu, one block (128 thr) per row
// ---------------------------------------------------------------------------
__global__ __launch_bounds__(128) void ln_kernel(const float* __restrict__ lnw,
                                                 const float* __restrict__ lnb,
                                                 float* __restrict__ out){
    const int row = blockIdx.x, tid = threadIdx.x;
    const float4 x = *(const float4*)(g_att + (size_t)row*DM + tid*4);
    float s  = x.x + x.y + x.z + x.w;
    float ss = fmaf(x.x, x.x, fmaf(x.y, x.y, fmaf(x.z, x.z, x.w*x.w)));
    #pragma unroll
    for (int o = 16; o > 0; o >>= 1){
        s  += __shfl_xor_sync(0xffffffffu, s,  o);
        ss += __shfl_xor_sync(0xffffffffu, ss, o);
    }
    __shared__ float red[8];
    int warp = tid >> 5, lane = tid & 31;
    if (lane == 0){ red[warp] = s; red[warp+4] = ss; }
    __syncthreads();
    s  = red[0] + red[1] + red[2] + red[3];
    ss = red[4] + red[5] + red[6] + red[7];
    float mu  = s * (1.0f/DM);
    float inv = rsqrtf(ss * (1.0f/DM) - mu*mu + 1e-5f);
    const float4 w = *(const float4*)(lnw + tid*4);
    const float4 bb = *(const float4*)(lnb + tid*4);
    float4 y;
    y.x = fmaxf((x.x - mu)*inv*w.x + bb.x, 0.f);
    y.y = fmaxf((x.y - mu)*inv*w.y + bb.y, 0.f);
    y.z = fmaxf((x.z - mu)*inv*w.z + bb.z, 0.f);
    y.w = fmaxf((x.w - mu)*inv*w.w + bb.w, 0.f);
    *(float4*)(out + (size_t)row*DM + tid*4) = y;
}

// ---------------------------------------------------------------------------
extern "C" void kernel_launch(void* const* d_in, const int* in_sizes, int n_in,
                              void* d_out, int out_size){
    const float* Q   = (const float*)d_in[0];
    const float* Wq  = (const float*)d_in[1];
    const float* bq  = (const float*)d_in[2];
    const float* Wk  = (const float*)d_in[3];
    const float* bk  = (const float*)d_in[4];
    const float* Wv  = (const float*)d_in[5];
    const float* bv  = (const float*)d_in[6];
    const float* lnw = (const float*)d_in[7];
    const float* lnb = (const float*)d_in[8];
    float* out = (float*)d_out;

    prep_q<<<NROWS/8, 256>>>(Q);
    prep_w<<<dim3(DM*DM/1024, 3), 256>>>(Wq, Wk, Wv);

    const int pj_smem = 3 * P_STG * 4;   // 110592
    cudaFuncSetAttribute(proj_kernel, cudaFuncAttributeMaxDynamicSharedMemorySize, pj_smem);
    proj_kernel<<<dim3(DM/128, NROWS/128, 3), 256, pj_smem>>>(bq, bk, bv);

    const int es_smem = (128*SQ_STR + 2*KT_U)*4 + SEQ*4 + 384*4;  // 110080
    cudaFuncSetAttribute(escore_kernel, cudaFuncAttributeMaxDynamicSharedMemorySize, es_smem);
    escore_kernel<<<dim3(SEQ/128, NH, NB), 256, es_smem>>>(out + OUT0);

    const int wv_smem = 3 * WV_STG * 4;  // 82944
    cudaFuncSetAttribute(wv_kernel, cudaFuncAttributeMaxDynamicSharedMemorySize, wv_smem);
    wv_kernel<<<dim3(SEQ/128, NH, NB), 256, wv_smem>>>(out + OUT0);

    ln_kernel<<<NROWS, 128>>>(lnw, lnb, out);
}